// round 2
// baseline (speedup 1.0000x reference)
#include <cuda_runtime.h>
#include <math.h>

#define E_CNT 262144
#define N_CNT 16384

// ---------------- device scratch (static, allocation-free) ----------------
__device__ float d_Q[N_CNT * 512];        // per-node Q (N,32,16)
__device__ float d_denom[N_CNT * 32];     // softmax denominators per (node,m)
__device__ float d_envacc[N_CNT * 128];   // sum of z*env_edges per (node,m,4)
__device__ float d_envnodes[N_CNT * 128]; // normalized env per node

// ---------------- init: zero accumulators every call ----------------
__global__ void k_init() {
    int total = N_CNT * 32 + N_CNT * 128;
    for (int i = blockIdx.x * blockDim.x + threadIdx.x; i < total;
         i += gridDim.x * blockDim.x) {
        if (i < N_CNT * 32) d_denom[i] = 0.f;
        else d_envacc[i - N_CNT * 32] = 0.f;
    }
}

// ---------------- per-node Q = node_invariants @ Wq  (N x 64 @ 64 x 512) ----------------
__global__ void k_q(const float* __restrict__ ninv, const float* __restrict__ Wq) {
    __shared__ float s[64];
    int n = blockIdx.x;
    int t = threadIdx.x; // 512 threads, 1 column each
    if (t < 64) s[t] = ninv[n * 64 + t];
    __syncthreads();
    float a = 0.f;
#pragma unroll 8
    for (int k = 0; k < 64; k++) a += s[k] * Wq[k * 512 + t];
    d_Q[n * 512 + t] = a;
}

// ---------------- edge phase A: K-GEMM + env gate + fused softmax-free attention scatter ----
// block: 256 threads, 32 edges. thread (rg = tid/32, m = tid%32) computes
// K[e, m*16 .. m*16+15] for 4 edges (e = rg*4..rg*4+3), plus the two W_env dots.
#define KC 8
__global__ __launch_bounds__(256, 2) void k_edgeA(
    const float* __restrict__ scal, const float* __restrict__ equiv,
    const float* __restrict__ W_env, const float* __restrict__ b_env,
    const float* __restrict__ Wk, const int* __restrict__ edge_center)
{
    __shared__ float sS[32 * 128];   // scalar tile
    __shared__ float sW[KC * 512];   // Wk chunk
    __shared__ float sWe[KC * 64];   // W_env chunk
    __shared__ int   sIdx[32];

    int tid = threadIdx.x;
    long e0 = (long)blockIdx.x * 32;

    { // load scalar tile (coalesced float4)
        const float4* src = (const float4*)(scal + e0 * 128);
        float4* dst = (float4*)sS;
        for (int i = tid; i < 32 * 32; i += 256) dst[i] = src[i];
        if (tid < 32) sIdx[tid] = edge_center[e0 + tid];
    }

    int m  = tid & 31;
    int rg = tid >> 5;

    float4 acc[4][4];
    float g0[4], g1[4];
#pragma unroll
    for (int i = 0; i < 4; i++) {
        g0[i] = 0.f; g1[i] = 0.f;
#pragma unroll
        for (int q = 0; q < 4; q++) acc[i][q] = make_float4(0.f, 0.f, 0.f, 0.f);
    }

    for (int kc = 0; kc < 128; kc += KC) {
        __syncthreads();
        { // stage Wk / W_env chunk
            const float4* src = (const float4*)(Wk + (long)kc * 512);
            float4* dst = (float4*)sW;
            for (int i = tid; i < KC * 128; i += 256) dst[i] = src[i];
            const float* we = W_env + (long)kc * 64;
            for (int i = tid; i < KC * 64; i += 256) sWe[i] = we[i];
        }
        __syncthreads();
#pragma unroll
        for (int kk = 0; kk < KC; kk++) {
            const float* wrow = &sW[kk * 512 + m * 16];
            float4 w0 = *(const float4*)(wrow + 0);
            float4 w1 = *(const float4*)(wrow + 4);
            float4 w2 = *(const float4*)(wrow + 8);
            float4 w3 = *(const float4*)(wrow + 12);
            float we0 = sWe[kk * 64 + 2 * m];
            float we1 = sWe[kk * 64 + 2 * m + 1];
#pragma unroll
            for (int i = 0; i < 4; i++) {
                float s = sS[(rg * 4 + i) * 128 + kc + kk];
                acc[i][0].x += s * w0.x; acc[i][0].y += s * w0.y;
                acc[i][0].z += s * w0.z; acc[i][0].w += s * w0.w;
                acc[i][1].x += s * w1.x; acc[i][1].y += s * w1.y;
                acc[i][1].z += s * w1.z; acc[i][1].w += s * w1.w;
                acc[i][2].x += s * w2.x; acc[i][2].y += s * w2.y;
                acc[i][2].z += s * w2.z; acc[i][2].w += s * w2.w;
                acc[i][3].x += s * w3.x; acc[i][3].y += s * w3.y;
                acc[i][3].z += s * w3.z; acc[i][3].w += s * w3.w;
                g0[i] += s * we0;
                g1[i] += s * we1;
            }
        }
    }

    float be0 = b_env[2 * m], be1 = b_env[2 * m + 1];
#pragma unroll
    for (int i = 0; i < 4; i++) {
        int el = rg * 4 + i;
        long e = e0 + el;
        int n  = sIdx[el];
        const float4* Qp = (const float4*)(d_Q + (long)n * 512 + m * 16);
        float lg = 0.f;
#pragma unroll
        for (int q = 0; q < 4; q++) {
            float4 qv = Qp[q];
            lg += acc[i][q].x * qv.x + acc[i][q].y * qv.y +
                  acc[i][q].z * qv.z + acc[i][q].w * qv.w;
        }
        lg *= 0.25f;                                  // INV_SQRTD
        lg = fminf(fmaxf(lg, -5.f), 5.f);             // CLIP
        float z = expf(lg);                           // shift-free softmax (valid: clipped)
        float a0 = g0[i] + be0, a1 = g1[i] + be1;
        float si0 = a0 / (1.f + expf(-a0));           // silu
        float si1 = a1 / (1.f + expf(-a1));
        float4 q4 = *(const float4*)(equiv + e * 128 + m * 4);
        float* base = &d_envacc[((long)n * 32 + m) * 4];
        atomicAdd(&d_denom[n * 32 + m], z);
        atomicAdd(base + 0, z * q4.x * si0);
        atomicAdd(base + 1, z * q4.y * si1);
        atomicAdd(base + 2, z * q4.z * si1);
        atomicAdd(base + 3, z * q4.w * si1);
    }
}

// ---------------- per-node: env = acc/denom, SO3 layernorm over EQ_SLICES ----------------
__global__ void k_node() {
    int n = blockIdx.x * 8 + (threadIdx.x >> 5);
    int m = threadIdx.x & 31;
    float den = d_denom[n * 32 + m];
    float inv = den > 0.f ? 1.f / den : 0.f;
    float4 a = *(float4*)&d_envacc[(n * 32 + m) * 4];
    a.x *= inv; a.y *= inv; a.z *= inv; a.w *= inv;
    float s0 = a.x * a.x;
    float s1 = a.y * a.y + a.z * a.z + a.w * a.w;
#pragma unroll
    for (int o = 16; o; o >>= 1) {
        s0 += __shfl_xor_sync(0xffffffffu, s0, o);
        s1 += __shfl_xor_sync(0xffffffffu, s1, o);
    }
    float r0 = rsqrtf(s0 * (1.f / 32.f) + 1e-6f);
    float r1 = rsqrtf(s1 * (1.f / 96.f) + 1e-6f);
    float4 o4 = make_float4(a.x * r0, a.y * r1, a.z * r1, a.w * r1);
    *(float4*)&d_envnodes[(n * 32 + m) * 4] = o4;
}

// ---------------- edge phase B: tensor product + TP layernorm + mix/sc GEMM + residual ----
// dynamic smem carve (floats): sWc 20480 | sB 256 | sF 32*80 | sTp 32*32*8
__global__ __launch_bounds__(256, 1) void k_edgeB(
    const float* __restrict__ scal, const float* __restrict__ equiv,
    const float* __restrict__ cond, const float* __restrict__ ucoef,
    const float* __restrict__ W_mix, const float* __restrict__ b_mix,
    const float* __restrict__ W_sc,  const float* __restrict__ b_sc,
    const int* __restrict__ edge_center, const int* __restrict__ active,
    float* __restrict__ out)
{
    extern __shared__ float sm[];
    float* sWc = sm;                  // [80][256] combined (W_mix | W_sc)
    float* sB  = sWc + 20480;         // [256]
    float* sF  = sB + 256;            // [32][80] feats
    float* sTp = sF + 2560;           // [32][32][8] normalized tp_out

    int tid = threadIdx.x;
    long e0 = (long)blockIdx.x * 32;

    for (int idx = tid; idx < 20480; idx += 256) {
        int i = idx >> 8, j = idx & 255;
        sWc[idx] = (j < 128) ? W_mix[i * 128 + j] : W_sc[i * 128 + (j - 128)];
    }
    sB[tid] = (tid < 128) ? b_mix[tid] : b_sc[tid - 128];
    for (int idx = tid; idx < 32 * 16; idx += 256) {
        int el = idx >> 4, i = idx & 15;
        sF[el * 80 + 64 + i] = cond[(e0 + el) * 16 + i];
    }

    { // phase 2: tp_out + TP layernorm + feats (warp = one edge at a time, lane = m)
        int w = tid >> 5, m = tid & 31;
        for (int rep = 0; rep < 4; rep++) {
            int el = w * 4 + rep;
            long e = e0 + el;
            int n = edge_center[e];
            float4 x = *(const float4*)(equiv + e * 128 + m * 4);
            float4 y = *(const float4*)(d_envnodes + (long)n * 128 + m * 4);
            float t0 = x.x * y.x;
            float t1 = x.x * y.y, t2 = x.x * y.z, t3 = x.x * y.w;
            float t4 = x.y * y.x, t5 = x.z * y.x, t6 = x.w * y.x;
            float t7 = (x.y * y.y + x.z * y.z + x.w * y.w) * 0.5773502691896258f;
            float s0 = t0 * t0;
            float s1 = t1 * t1 + t2 * t2 + t3 * t3;
            float s2 = t4 * t4 + t5 * t5 + t6 * t6;
            float s3 = t7 * t7;
#pragma unroll
            for (int o = 16; o; o >>= 1) {
                s0 += __shfl_xor_sync(0xffffffffu, s0, o);
                s1 += __shfl_xor_sync(0xffffffffu, s1, o);
                s2 += __shfl_xor_sync(0xffffffffu, s2, o);
                s3 += __shfl_xor_sync(0xffffffffu, s3, o);
            }
            float r0 = rsqrtf(s0 * (1.f / 32.f) + 1e-6f);
            float r1 = rsqrtf(s1 * (1.f / 96.f) + 1e-6f);
            float r2 = rsqrtf(s2 * (1.f / 96.f) + 1e-6f);
            float r3 = rsqrtf(s3 * (1.f / 32.f) + 1e-6f);
            t0 *= r0; t1 *= r1; t2 *= r1; t3 *= r1;
            t4 *= r2; t5 *= r2; t6 *= r2; t7 *= r3;
            float* tp = &sTp[(el * 32 + m) * 8];
            tp[0] = t0; tp[1] = t1; tp[2] = t2; tp[3] = t3;
            tp[4] = t4; tp[5] = t5; tp[6] = t6; tp[7] = t7;
            sF[el * 80 + m]      = t0;
            sF[el * 80 + 32 + m] = t7;
        }
    }
    __syncthreads();

    // phase 3: F[32][80] @ Wc[80][256]  (thread: 8 edges x 4 cols)
    int tCol = tid & 63, tRow = tid >> 6;
    float4 acc8[8];
    float4 bias4 = ((float4*)sB)[tCol];
#pragma unroll
    for (int i = 0; i < 8; i++) acc8[i] = bias4;
    for (int k = 0; k < 80; k++) {
        float4 w4 = ((float4*)(sWc + k * 256))[tCol];
#pragma unroll
        for (int i = 0; i < 8; i++) {
            float f = sF[(tRow * 8 + i) * 80 + k];
            acc8[i].x += f * w4.x; acc8[i].y += f * w4.y;
            acc8[i].z += f * w4.z; acc8[i].w += f * w4.w;
        }
    }

    float u = ucoef[0];
    float c_old = rsqrtf(u * u + 1.f);
    float c_new = u * c_old;

#pragma unroll
    for (int i = 0; i < 8; i++) {
        int el = tRow * 8 + i;
        long e = e0 + el;
        long r = active[e];   // permutation (arange) in this dataset
        float4 a = acc8[i];
        if (tCol < 32) {      // cols [0,128): mix[m][0..3], m == tCol
            int m2 = tCol;
            float* tp = &sTp[(el * 32 + m2) * 8];
            float4 ne;
            ne.x = a.x * tp[0] + a.y * tp[7];
            ne.y = a.z * tp[1] + a.w * tp[4];
            ne.z = a.z * tp[2] + a.w * tp[5];
            ne.w = a.z * tp[3] + a.w * tp[6];
            float4 b = *(const float4*)(equiv + r * 128 + m2 * 4);
            float4 o;
            o.x = c_old * b.x + c_new * ne.x;
            o.y = c_old * b.y + c_new * ne.y;
            o.z = c_old * b.z + c_new * ne.z;
            o.w = c_old * b.w + c_new * ne.w;
            *(float4*)(out + (long)E_CNT * 128 + r * 128 + m2 * 4) = o;
        } else {              // cols [128,256): new_scalar
            int jc = tCol - 32;
            float4 b = *(const float4*)(scal + r * 128 + jc * 4);
            float4 o;
            o.x = c_old * b.x + c_new * a.x;
            o.y = c_old * b.y + c_new * a.y;
            o.z = c_old * b.z + c_new * a.z;
            o.w = c_old * b.w + c_new * a.w;
            *(float4*)(out + r * 128 + jc * 4) = o;
        }
    }
}

// ---------------- launch ----------------
extern "C" void kernel_launch(void* const* d_in, const int* in_sizes, int n_in,
                              void* d_out, int out_size)
{
    const float* scal  = (const float*)d_in[0];
    const float* equiv = (const float*)d_in[1];
    const float* ninv  = (const float*)d_in[2];
    const float* cond  = (const float*)d_in[3];
    const float* ucoef = (const float*)d_in[4];
    const float* W_env = (const float*)d_in[5];
    const float* b_env = (const float*)d_in[6];
    const float* Wq    = (const float*)d_in[7];
    const float* Wk    = (const float*)d_in[8];
    const float* W_mix = (const float*)d_in[9];
    const float* b_mix = (const float*)d_in[10];
    const float* W_sc  = (const float*)d_in[11];
    const float* b_sc  = (const float*)d_in[12];
    const int*   ec    = (const int*)d_in[13];
    const int*   act   = (const int*)d_in[14];
    float* out = (float*)d_out;

    k_init<<<512, 1024>>>();
    k_q<<<N_CNT, 512>>>(ninv, Wq);
    k_edgeA<<<E_CNT / 32, 256>>>(scal, equiv, W_env, b_env, Wk, ec);
    k_node<<<N_CNT / 8, 256>>>();

    const int SMEMB = (20480 + 256 + 2560 + 8192) * 4;
    cudaFuncSetAttribute(k_edgeB, cudaFuncAttributeMaxDynamicSharedMemorySize, SMEMB);
    k_edgeB<<<E_CNT / 32, 256, SMEMB>>>(scal, equiv, cond, ucoef,
                                        W_mix, b_mix, W_sc, b_sc, ec, act, out);
}

// round 3
// speedup vs baseline: 2.3725x; 2.3725x over previous
#include <cuda_runtime.h>
#include <math.h>

#define E_CNT 262144
#define N_CNT 16384

// ---------------- device scratch (static, allocation-free) ----------------
__device__ float d_Q[N_CNT * 512];                 // per-node Q (N,32,16)
__device__ float d_P[(size_t)N_CNT * 4096];        // P[n][k][m]  (256 MB)
__device__ float d_envnodes[N_CNT * 128];          // normalized env per node
__device__ int   d_cnt[N_CNT];
__device__ int   d_off[N_CNT + 1];
__device__ int   d_cur[N_CNT];
__device__ int   d_eid[E_CNT];

// ---------------- CSR build ----------------
__global__ void k_zero() {
    int i = blockIdx.x * blockDim.x + threadIdx.x;
    if (i < N_CNT) d_cnt[i] = 0;
}
__global__ void k_hist(const int* __restrict__ ec) {
    int e = blockIdx.x * blockDim.x + threadIdx.x;
    if (e < E_CNT) atomicAdd(&d_cnt[ec[e]], 1);
}
__global__ void k_scan() {
    __shared__ int part[1024];
    int t = threadIdx.x;
    int base = t * 16;
    int loc[16];
    int s = 0;
#pragma unroll
    for (int i = 0; i < 16; i++) { loc[i] = s; s += d_cnt[base + i]; }
    part[t] = s;
    __syncthreads();
    for (int o = 1; o < 1024; o <<= 1) {
        int v = (t >= o) ? part[t - o] : 0;
        __syncthreads();
        part[t] += v;
        __syncthreads();
    }
    int excl = (t > 0) ? part[t - 1] : 0;
#pragma unroll
    for (int i = 0; i < 16; i++) {
        d_off[base + i] = excl + loc[i];
        d_cur[base + i] = excl + loc[i];
    }
    if (t == 1023) d_off[N_CNT] = part[1023];
}
__global__ void k_scatter(const int* __restrict__ ec) {
    int e = blockIdx.x * blockDim.x + threadIdx.x;
    if (e < E_CNT) {
        int n = ec[e];
        int pos = atomicAdd(&d_cur[n], 1);
        d_eid[pos] = e;
    }
}

// ---------------- per-node Q = node_invariants @ Wq  (N x 64 @ 64 x 512) --------
__global__ void k_q(const float* __restrict__ ninv, const float* __restrict__ Wq) {
    __shared__ float s[64];
    int n = blockIdx.x;
    int t = threadIdx.x;
    if (t < 64) s[t] = ninv[n * 64 + t];
    __syncthreads();
    float a = 0.f;
#pragma unroll 8
    for (int k = 0; k < 64; k++) a += s[k] * Wq[k * 512 + t];
    d_Q[n * 512 + t] = a;
}

// ---------------- P[n][k][m] = sum_d Wk[k, m*16+d] * Q[n, m*16+d] ----------------
// block: 256 threads = 32 m x 8 node-slots, 4 nodes per slot -> 32 nodes/block.
__global__ __launch_bounds__(256) void k_P(const float* __restrict__ Wk) {
    __shared__ float sW[16 * 512];   // 32 KB chunk of Wk
    int tid = threadIdx.x;
    int m = tid & 31, ns = tid >> 5;
    int n0 = blockIdx.x * 32;

    float q[4][16];
#pragma unroll
    for (int j = 0; j < 4; j++) {
        int n = n0 + ns * 4 + j;
        const float4* Qp = (const float4*)(d_Q + (size_t)n * 512 + m * 16);
#pragma unroll
        for (int v = 0; v < 4; v++) {
            float4 t = Qp[v];
            q[j][v * 4 + 0] = t.x; q[j][v * 4 + 1] = t.y;
            q[j][v * 4 + 2] = t.z; q[j][v * 4 + 3] = t.w;
        }
    }

    for (int kc = 0; kc < 128; kc += 16) {
        __syncthreads();
        {
            const float4* src = (const float4*)(Wk + (size_t)kc * 512);
            float4* dst = (float4*)sW;
            for (int i = tid; i < 2048; i += 256) dst[i] = src[i];
        }
        __syncthreads();
#pragma unroll
        for (int kk = 0; kk < 16; kk++) {
            const float* wr = &sW[kk * 512 + m * 16];
            float4 w0 = *(const float4*)(wr + 0);
            float4 w1 = *(const float4*)(wr + 4);
            float4 w2 = *(const float4*)(wr + 8);
            float4 w3 = *(const float4*)(wr + 12);
#pragma unroll
            for (int j = 0; j < 4; j++) {
                float acc = q[j][0] * w0.x + q[j][1] * w0.y + q[j][2] * w0.z + q[j][3] * w0.w
                          + q[j][4] * w1.x + q[j][5] * w1.y + q[j][6] * w1.z + q[j][7] * w1.w
                          + q[j][8] * w2.x + q[j][9] * w2.y + q[j][10] * w2.z + q[j][11] * w2.w
                          + q[j][12] * w3.x + q[j][13] * w3.y + q[j][14] * w3.z + q[j][15] * w3.w;
                int n = n0 + ns * 4 + j;
                d_P[(size_t)n * 4096 + (kc + kk) * 32 + m] = acc;
            }
        }
    }
}

// ---------------- per-node fused: gate + logits(P) + softmax + env agg + SO3 norm -----
// block per node, 128 threads = 16 mg (2 m each) x 8 es (2 edges each) -> 16 edges/chunk.
// dyn smem carve (floats): P_s 4096 | W_s 8192 | scal_s 128*17 | acc_s 256 | eids 16(int)
__global__ __launch_bounds__(128, 3) void k_nodeA(
    const float* __restrict__ scal, const float* __restrict__ equiv,
    const float* __restrict__ W_env, const float* __restrict__ b_env)
{
    extern __shared__ float sm[];
    float* P_s    = sm;                 // [k][m] 4096
    float* W_s    = P_s + 4096;         // [k][64] 8192
    float* scal_s = W_s + 8192;         // [k][17] 2176 (pad 17 -> conflict-free)
    float* acc_s  = scal_s + 2176;      // [m][8]  256
    int*   eids   = (int*)(acc_s + 256);

    int n = blockIdx.x;
    int tid = threadIdx.x;
    int beg = d_off[n];
    int cnt = d_off[n + 1] - beg;

    {
        const float4* Pg = (const float4*)(d_P + (size_t)n * 4096);
        float4* Pd = (float4*)P_s;
        for (int i = tid; i < 1024; i += 128) Pd[i] = Pg[i];
        const float4* Wg = (const float4*)W_env;
        float4* Wd = (float4*)W_s;
        for (int i = tid; i < 2048; i += 128) Wd[i] = Wg[i];
        for (int i = tid; i < 256; i += 128) acc_s[i] = 0.f;
    }

    int mg = tid >> 3, es = tid & 7;
    int m0 = mg * 2;
    float be0 = b_env[2 * m0 + 0], be1 = b_env[2 * m0 + 1];
    float be2 = b_env[2 * m0 + 2], be3 = b_env[2 * m0 + 3];

    for (int base = 0; base < cnt; base += 16) {
        __syncthreads();
        if (tid < 16) {
            int idx = base + tid;
            eids[tid] = (idx < cnt) ? d_eid[beg + idx] : -1;
        }
        __syncthreads();
        for (int i = tid; i < 512; i += 128) {
            int el = i >> 5, c = i & 31;
            int e = eids[el];
            float4 v = make_float4(0.f, 0.f, 0.f, 0.f);
            if (e >= 0) v = ((const float4*)scal)[(size_t)e * 32 + c];
            scal_s[(4 * c + 0) * 17 + el] = v.x;
            scal_s[(4 * c + 1) * 17 + el] = v.y;
            scal_s[(4 * c + 2) * 17 + el] = v.z;
            scal_s[(4 * c + 3) * 17 + el] = v.w;
        }
        __syncthreads();

        int ei0 = es * 2, ei1 = ei0 + 1;
        float lg00 = 0, lg01 = 0, lg10 = 0, lg11 = 0;
        float g000 = 0, g001 = 0, g010 = 0, g011 = 0;
        float g100 = 0, g101 = 0, g110 = 0, g111 = 0;
#pragma unroll 4
        for (int k = 0; k < 128; k++) {
            float2 p = *(const float2*)&P_s[k * 32 + m0];
            float4 w = *(const float4*)&W_s[k * 64 + 2 * m0];
            float a = scal_s[k * 17 + ei0];
            float b = scal_s[k * 17 + ei1];
            lg00 += a * p.x; lg01 += a * p.y;
            lg10 += b * p.x; lg11 += b * p.y;
            g000 += a * w.x; g001 += a * w.y; g010 += a * w.z; g011 += a * w.w;
            g100 += b * w.x; g101 += b * w.y; g110 += b * w.z; g111 += b * w.w;
        }

        float r0=0,r1=0,r2=0,r3=0,r4=0;   // m0:   den, env.xyzw
        float r5=0,r6=0,r7=0,r8=0,r9=0;   // m0+1
        int e0 = eids[ei0], e1 = eids[ei1];
        if (e0 >= 0) {
            float z0 = __expf(fminf(fmaxf(lg00 * 0.25f, -5.f), 5.f));
            float z1 = __expf(fminf(fmaxf(lg01 * 0.25f, -5.f), 5.f));
            float a0 = g000 + be0, a1 = g001 + be1, a2 = g010 + be2, a3 = g011 + be3;
            float s0 = a0 / (1.f + __expf(-a0)), s1 = a1 / (1.f + __expf(-a1));
            float s2 = a2 / (1.f + __expf(-a2)), s3 = a3 / (1.f + __expf(-a3));
            float4 q0 = ((const float4*)equiv)[(size_t)e0 * 32 + m0];
            float4 q1 = ((const float4*)equiv)[(size_t)e0 * 32 + m0 + 1];
            r0 += z0; r1 += z0*q0.x*s0; r2 += z0*q0.y*s1; r3 += z0*q0.z*s1; r4 += z0*q0.w*s1;
            r5 += z1; r6 += z1*q1.x*s2; r7 += z1*q1.y*s3; r8 += z1*q1.z*s3; r9 += z1*q1.w*s3;
        }
        if (e1 >= 0) {
            float z0 = __expf(fminf(fmaxf(lg10 * 0.25f, -5.f), 5.f));
            float z1 = __expf(fminf(fmaxf(lg11 * 0.25f, -5.f), 5.f));
            float a0 = g100 + be0, a1 = g101 + be1, a2 = g110 + be2, a3 = g111 + be3;
            float s0 = a0 / (1.f + __expf(-a0)), s1 = a1 / (1.f + __expf(-a1));
            float s2 = a2 / (1.f + __expf(-a2)), s3 = a3 / (1.f + __expf(-a3));
            float4 q0 = ((const float4*)equiv)[(size_t)e1 * 32 + m0];
            float4 q1 = ((const float4*)equiv)[(size_t)e1 * 32 + m0 + 1];
            r0 += z0; r1 += z0*q0.x*s0; r2 += z0*q0.y*s1; r3 += z0*q0.z*s1; r4 += z0*q0.w*s1;
            r5 += z1; r6 += z1*q1.x*s2; r7 += z1*q1.y*s3; r8 += z1*q1.z*s3; r9 += z1*q1.w*s3;
        }
#pragma unroll
        for (int o = 1; o <= 4; o <<= 1) {
            r0 += __shfl_xor_sync(0xffffffffu, r0, o);
            r1 += __shfl_xor_sync(0xffffffffu, r1, o);
            r2 += __shfl_xor_sync(0xffffffffu, r2, o);
            r3 += __shfl_xor_sync(0xffffffffu, r3, o);
            r4 += __shfl_xor_sync(0xffffffffu, r4, o);
            r5 += __shfl_xor_sync(0xffffffffu, r5, o);
            r6 += __shfl_xor_sync(0xffffffffu, r6, o);
            r7 += __shfl_xor_sync(0xffffffffu, r7, o);
            r8 += __shfl_xor_sync(0xffffffffu, r8, o);
            r9 += __shfl_xor_sync(0xffffffffu, r9, o);
        }
        if (es == 0) {
            acc_s[m0 * 8 + 0] += r0; acc_s[m0 * 8 + 1] += r1;
            acc_s[m0 * 8 + 2] += r2; acc_s[m0 * 8 + 3] += r3;
            acc_s[m0 * 8 + 4] += r4;
            acc_s[(m0 + 1) * 8 + 0] += r5; acc_s[(m0 + 1) * 8 + 1] += r6;
            acc_s[(m0 + 1) * 8 + 2] += r7; acc_s[(m0 + 1) * 8 + 3] += r8;
            acc_s[(m0 + 1) * 8 + 4] += r9;
        }
    }
    __syncthreads();

    if (tid < 32) {
        int m = tid;
        float den = acc_s[m * 8 + 0];
        float inv = den > 0.f ? 1.f / den : 0.f;
        float ax = acc_s[m * 8 + 1] * inv, ay = acc_s[m * 8 + 2] * inv;
        float az = acc_s[m * 8 + 3] * inv, aw = acc_s[m * 8 + 4] * inv;
        float s0 = ax * ax;
        float s1 = ay * ay + az * az + aw * aw;
#pragma unroll
        for (int o = 16; o; o >>= 1) {
            s0 += __shfl_xor_sync(0xffffffffu, s0, o);
            s1 += __shfl_xor_sync(0xffffffffu, s1, o);
        }
        float n0 = rsqrtf(s0 * (1.f / 32.f) + 1e-6f);
        float n1 = rsqrtf(s1 * (1.f / 96.f) + 1e-6f);
        *(float4*)&d_envnodes[(size_t)n * 128 + m * 4] =
            make_float4(ax * n0, ay * n1, az * n1, aw * n1);
    }
}

// ---------------- edge phase B: tensor product + TP layernorm + mix/sc GEMM + residual ----
// 512 threads, 64 edges per block. dyn smem (floats): sWc 20480 | sB 256 | sF 64*80 | sTp 64*32*8
__global__ __launch_bounds__(512, 1) void k_edgeB(
    const float* __restrict__ scal, const float* __restrict__ equiv,
    const float* __restrict__ cond, const float* __restrict__ ucoef,
    const float* __restrict__ W_mix, const float* __restrict__ b_mix,
    const float* __restrict__ W_sc,  const float* __restrict__ b_sc,
    const int* __restrict__ edge_center, const int* __restrict__ active,
    float* __restrict__ out)
{
    extern __shared__ float sm[];
    float* sWc = sm;                  // [80][256] combined (W_mix | W_sc)
    float* sB  = sWc + 20480;         // [256]
    float* sF  = sB + 256;            // [64][80] feats
    float* sTp = sF + 5120;           // [64][32][8] normalized tp_out

    int tid = threadIdx.x;
    long e0 = (long)blockIdx.x * 64;

    for (int idx = tid; idx < 20480; idx += 512) {
        int i = idx >> 8, j = idx & 255;
        sWc[idx] = (j < 128) ? W_mix[i * 128 + j] : W_sc[i * 128 + (j - 128)];
    }
    if (tid < 256) sB[tid] = (tid < 128) ? b_mix[tid] : b_sc[tid - 128];
    for (int idx = tid; idx < 64 * 16; idx += 512) {
        int el = idx >> 4, i = idx & 15;
        sF[el * 80 + 64 + i] = cond[(e0 + el) * 16 + i];
    }

    { // phase 2: tp_out + TP layernorm + feats (warp per edge, lane = m)
        int w = tid >> 5, m = tid & 31;
        for (int rep = 0; rep < 4; rep++) {
            int el = w * 4 + rep;
            long e = e0 + el;
            int nidx = edge_center[e];
            float4 x = *(const float4*)(equiv + e * 128 + m * 4);
            float4 y = *(const float4*)(d_envnodes + (size_t)nidx * 128 + m * 4);
            float t0 = x.x * y.x;
            float t1 = x.x * y.y, t2 = x.x * y.z, t3 = x.x * y.w;
            float t4 = x.y * y.x, t5 = x.z * y.x, t6 = x.w * y.x;
            float t7 = (x.y * y.y + x.z * y.z + x.w * y.w) * 0.5773502691896258f;
            float s0 = t0 * t0;
            float s1 = t1 * t1 + t2 * t2 + t3 * t3;
            float s2 = t4 * t4 + t5 * t5 + t6 * t6;
            float s3 = t7 * t7;
#pragma unroll
            for (int o = 16; o; o >>= 1) {
                s0 += __shfl_xor_sync(0xffffffffu, s0, o);
                s1 += __shfl_xor_sync(0xffffffffu, s1, o);
                s2 += __shfl_xor_sync(0xffffffffu, s2, o);
                s3 += __shfl_xor_sync(0xffffffffu, s3, o);
            }
            float r0 = rsqrtf(s0 * (1.f / 32.f) + 1e-6f);
            float r1 = rsqrtf(s1 * (1.f / 96.f) + 1e-6f);
            float r2 = rsqrtf(s2 * (1.f / 96.f) + 1e-6f);
            float r3 = rsqrtf(s3 * (1.f / 32.f) + 1e-6f);
            t0 *= r0; t1 *= r1; t2 *= r1; t3 *= r1;
            t4 *= r2; t5 *= r2; t6 *= r2; t7 *= r3;
            float* tp = &sTp[(el * 32 + m) * 8];
            tp[0] = t0; tp[1] = t1; tp[2] = t2; tp[3] = t3;
            tp[4] = t4; tp[5] = t5; tp[6] = t6; tp[7] = t7;
            sF[el * 80 + m]      = t0;
            sF[el * 80 + 32 + m] = t7;
        }
    }
    __syncthreads();

    // phase 3: F[64][80] @ Wc[80][256]  (thread: 8 edges x 4 cols)
    int tCol = tid & 63, tRow = tid >> 6;
    float4 acc8[8];
    float4 bias4 = ((float4*)sB)[tCol];
#pragma unroll
    for (int i = 0; i < 8; i++) acc8[i] = bias4;
    for (int k = 0; k < 80; k++) {
        float4 w4 = ((float4*)(sWc + k * 256))[tCol];
#pragma unroll
        for (int i = 0; i < 8; i++) {
            float f = sF[(tRow * 8 + i) * 80 + k];
            acc8[i].x += f * w4.x; acc8[i].y += f * w4.y;
            acc8[i].z += f * w4.z; acc8[i].w += f * w4.w;
        }
    }

    float u = ucoef[0];
    float c_old = rsqrtf(u * u + 1.f);
    float c_new = u * c_old;

#pragma unroll
    for (int i = 0; i < 8; i++) {
        int el = tRow * 8 + i;
        long e = e0 + el;
        long r = active[e];
        float4 a = acc8[i];
        if (tCol < 32) {      // cols [0,128): mix[m][0..3], m == tCol
            int m2 = tCol;
            float* tp = &sTp[(el * 32 + m2) * 8];
            float4 ne;
            ne.x = a.x * tp[0] + a.y * tp[7];
            ne.y = a.z * tp[1] + a.w * tp[4];
            ne.z = a.z * tp[2] + a.w * tp[5];
            ne.w = a.z * tp[3] + a.w * tp[6];
            float4 b = *(const float4*)(equiv + r * 128 + m2 * 4);
            float4 o;
            o.x = c_old * b.x + c_new * ne.x;
            o.y = c_old * b.y + c_new * ne.y;
            o.z = c_old * b.z + c_new * ne.z;
            o.w = c_old * b.w + c_new * ne.w;
            *(float4*)(out + (long)E_CNT * 128 + r * 128 + m2 * 4) = o;
        } else {              // cols [128,256): new_scalar
            int jc = tCol - 32;
            float4 b = *(const float4*)(scal + r * 128 + jc * 4);
            float4 o;
            o.x = c_old * b.x + c_new * a.x;
            o.y = c_old * b.y + c_new * a.y;
            o.z = c_old * b.z + c_new * a.z;
            o.w = c_old * b.w + c_new * a.w;
            *(float4*)(out + r * 128 + jc * 4) = o;
        }
    }
}

// ---------------- launch ----------------
extern "C" void kernel_launch(void* const* d_in, const int* in_sizes, int n_in,
                              void* d_out, int out_size)
{
    const float* scal  = (const float*)d_in[0];
    const float* equiv = (const float*)d_in[1];
    const float* ninv  = (const float*)d_in[2];
    const float* cond  = (const float*)d_in[3];
    const float* ucoef = (const float*)d_in[4];
    const float* W_env = (const float*)d_in[5];
    const float* b_env = (const float*)d_in[6];
    const float* Wq    = (const float*)d_in[7];
    const float* Wk    = (const float*)d_in[8];
    const float* W_mix = (const float*)d_in[9];
    const float* b_mix = (const float*)d_in[10];
    const float* W_sc  = (const float*)d_in[11];
    const float* b_sc  = (const float*)d_in[12];
    const int*   ec    = (const int*)d_in[13];
    const int*   act   = (const int*)d_in[14];
    float* out = (float*)d_out;

    // CSR build
    k_zero<<<64, 256>>>();
    k_hist<<<E_CNT / 256, 256>>>(ec);
    k_scan<<<1, 1024>>>();
    k_scatter<<<E_CNT / 256, 256>>>(ec);

    // Q per node, then P factorization
    k_q<<<N_CNT, 512>>>(ninv, Wq);
    k_P<<<N_CNT / 32, 256>>>(Wk);

    // fused per-node attention/env
    const int SMEMA = (4096 + 8192 + 2176 + 256 + 16) * 4;
    cudaFuncSetAttribute(k_nodeA, cudaFuncAttributeMaxDynamicSharedMemorySize, SMEMA);
    k_nodeA<<<N_CNT, 128, SMEMA>>>(scal, equiv, W_env, b_env);

    // edge phase B
    const int SMEMB = (20480 + 256 + 5120 + 16384) * 4;
    cudaFuncSetAttribute(k_edgeB, cudaFuncAttributeMaxDynamicSharedMemorySize, SMEMB);
    k_edgeB<<<E_CNT / 64, 512, SMEMB>>>(scal, equiv, cond, ucoef,
                                        W_mix, b_mix, W_sc, b_sc, ec, act, out);
}

// round 4
// speedup vs baseline: 2.4158x; 1.0182x over previous
#include <cuda_runtime.h>
#include <math.h>

#define E_CNT 262144
#define N_CNT 16384

// ---------------- f32x2 packed-FMA helpers (bit-exact fp32, 2x issue density) ----
__device__ __forceinline__ unsigned long long pk2(float lo, float hi) {
    unsigned long long r;
    asm("mov.b64 %0, {%1, %2};" : "=l"(r) : "f"(lo), "f"(hi));
    return r;
}
__device__ __forceinline__ void fma2(unsigned long long& d,
                                     unsigned long long a, unsigned long long b) {
    asm("fma.rn.f32x2 %0, %1, %2, %0;" : "+l"(d) : "l"(a), "l"(b));
}
__device__ __forceinline__ float2 upk2(unsigned long long v) {
    float2 f;
    asm("mov.b64 {%0, %1}, %2;" : "=f"(f.x), "=f"(f.y) : "l"(v));
    return f;
}

// ---------------- device scratch (static, allocation-free) ----------------
__device__ float d_Q[N_CNT * 512];                 // per-node Q (N,32,16)
__device__ float d_P[(size_t)N_CNT * 4096];        // P[n][k][m]
__device__ float d_envnodes[N_CNT * 128];          // normalized env per node
__device__ int   d_cnt[N_CNT];
__device__ int   d_off[N_CNT + 1];
__device__ int   d_cur[N_CNT];
__device__ int   d_eid[E_CNT];

// ---------------- CSR build ----------------
__global__ void k_zero() {
    int i = blockIdx.x * blockDim.x + threadIdx.x;
    if (i < N_CNT) d_cnt[i] = 0;
}
__global__ void k_hist(const int* __restrict__ ec) {
    int e = blockIdx.x * blockDim.x + threadIdx.x;
    if (e < E_CNT) atomicAdd(&d_cnt[ec[e]], 1);
}
__global__ void k_scan() {
    __shared__ int part[1024];
    int t = threadIdx.x;
    int base = t * 16;
    int loc[16];
    int s = 0;
#pragma unroll
    for (int i = 0; i < 16; i++) { loc[i] = s; s += d_cnt[base + i]; }
    part[t] = s;
    __syncthreads();
    for (int o = 1; o < 1024; o <<= 1) {
        int v = (t >= o) ? part[t - o] : 0;
        __syncthreads();
        part[t] += v;
        __syncthreads();
    }
    int excl = (t > 0) ? part[t - 1] : 0;
#pragma unroll
    for (int i = 0; i < 16; i++) {
        d_off[base + i] = excl + loc[i];
        d_cur[base + i] = excl + loc[i];
    }
    if (t == 1023) d_off[N_CNT] = part[1023];
}
__global__ void k_scatter(const int* __restrict__ ec) {
    int e = blockIdx.x * blockDim.x + threadIdx.x;
    if (e < E_CNT) {
        int n = ec[e];
        int pos = atomicAdd(&d_cur[n], 1);
        d_eid[pos] = e;
    }
}

// ---------------- per-node Q = node_invariants @ Wq  (N x 64 @ 64 x 512) --------
__global__ void k_q(const float* __restrict__ ninv, const float* __restrict__ Wq) {
    __shared__ float s[64];
    int n = blockIdx.x;
    int t = threadIdx.x;
    if (t < 64) s[t] = ninv[n * 64 + t];
    __syncthreads();
    float a = 0.f;
#pragma unroll 8
    for (int k = 0; k < 64; k++) a += s[k] * Wq[k * 512 + t];
    d_Q[n * 512 + t] = a;
}

// ---------------- P[n][k][m] = sum_d Wk[k, m*16+d] * Q[n, m*16+d] ----------------
__global__ __launch_bounds__(256) void k_P(const float* __restrict__ Wk) {
    __shared__ float sW[16 * 512];
    int tid = threadIdx.x;
    int m = tid & 31, ns = tid >> 5;
    int n0 = blockIdx.x * 32;

    float q[4][16];
#pragma unroll
    for (int j = 0; j < 4; j++) {
        int n = n0 + ns * 4 + j;
        const float4* Qp = (const float4*)(d_Q + (size_t)n * 512 + m * 16);
#pragma unroll
        for (int v = 0; v < 4; v++) {
            float4 t = Qp[v];
            q[j][v * 4 + 0] = t.x; q[j][v * 4 + 1] = t.y;
            q[j][v * 4 + 2] = t.z; q[j][v * 4 + 3] = t.w;
        }
    }

    for (int kc = 0; kc < 128; kc += 16) {
        __syncthreads();
        {
            const float4* src = (const float4*)(Wk + (size_t)kc * 512);
            float4* dst = (float4*)sW;
            for (int i = tid; i < 2048; i += 256) dst[i] = src[i];
        }
        __syncthreads();
#pragma unroll
        for (int kk = 0; kk < 16; kk++) {
            const float* wr = &sW[kk * 512 + m * 16];
            float4 w0 = *(const float4*)(wr + 0);
            float4 w1 = *(const float4*)(wr + 4);
            float4 w2 = *(const float4*)(wr + 8);
            float4 w3 = *(const float4*)(wr + 12);
#pragma unroll
            for (int j = 0; j < 4; j++) {
                float acc = q[j][0] * w0.x + q[j][1] * w0.y + q[j][2] * w0.z + q[j][3] * w0.w
                          + q[j][4] * w1.x + q[j][5] * w1.y + q[j][6] * w1.z + q[j][7] * w1.w
                          + q[j][8] * w2.x + q[j][9] * w2.y + q[j][10] * w2.z + q[j][11] * w2.w
                          + q[j][12] * w3.x + q[j][13] * w3.y + q[j][14] * w3.z + q[j][15] * w3.w;
                int n = n0 + ns * 4 + j;
                d_P[(size_t)n * 4096 + (kc + kk) * 32 + m] = acc;
            }
        }
    }
}

// ---------------- per-node fused: gate + logits(P) + softmax + env agg + SO3 norm -----
// block per node, 128 threads = 16 mg (2 m each) x 8 es (2 edges each) -> 16 edges/chunk.
// dyn smem carve (floats): P_s 4096 | W_s 8192 | scal_s 128*34 | acc_s 256 | eids 16(int)
__global__ __launch_bounds__(128, 3) void k_nodeA(
    const float* __restrict__ scal, const float* __restrict__ equiv,
    const float* __restrict__ W_env, const float* __restrict__ b_env)
{
    extern __shared__ float sm[];
    float* P_s    = sm;                 // [k][m] 4096
    float* W_s    = P_s + 4096;         // [k][64] 8192
    float* scal_s = W_s + 8192;         // [k][34] pairs (edge ei0, ei1) per es
    float* acc_s  = scal_s + 4352;      // [m][8]  256
    int*   eids   = (int*)(acc_s + 256);

    int n = blockIdx.x;
    int tid = threadIdx.x;
    int beg = d_off[n];
    int cnt = d_off[n + 1] - beg;

    {
        const float4* Pg = (const float4*)(d_P + (size_t)n * 4096);
        float4* Pd = (float4*)P_s;
        for (int i = tid; i < 1024; i += 128) Pd[i] = Pg[i];
        const float4* Wg = (const float4*)W_env;
        float4* Wd = (float4*)W_s;
        for (int i = tid; i < 2048; i += 128) Wd[i] = Wg[i];
        for (int i = tid; i < 256; i += 128) acc_s[i] = 0.f;
    }

    int mg = tid >> 3, es = tid & 7;
    int m0 = mg * 2;
    float be0 = b_env[2 * m0 + 0], be1 = b_env[2 * m0 + 1];
    float be2 = b_env[2 * m0 + 2], be3 = b_env[2 * m0 + 3];

    for (int base = 0; base < cnt; base += 16) {
        __syncthreads();
        if (tid < 16) {
            int idx = base + tid;
            eids[tid] = (idx < cnt) ? d_eid[beg + idx] : -1;
        }
        __syncthreads();
        for (int i = tid; i < 512; i += 128) {
            int el = i >> 5, c = i & 31;
            int e = eids[el];
            float4 v = make_float4(0.f, 0.f, 0.f, 0.f);
            if (e >= 0) v = ((const float4*)scal)[(size_t)e * 32 + c];
            scal_s[(4 * c + 0) * 34 + el] = v.x;
            scal_s[(4 * c + 1) * 34 + el] = v.y;
            scal_s[(4 * c + 2) * 34 + el] = v.z;
            scal_s[(4 * c + 3) * 34 + el] = v.w;
        }
        __syncthreads();

        // f32x2 packed GEMV: lg pairs over (m0,m0+1), gate pairs over channels
        unsigned long long lg0 = 0ull, lg1 = 0ull;            // edge a, edge b
        unsigned long long g0A = 0ull, g0B = 0ull;            // edge a: (m0 ch0,ch1),(m0+1 ch0,ch1)
        unsigned long long g1A = 0ull, g1B = 0ull;            // edge b
#pragma unroll 4
        for (int k = 0; k < 128; k++) {
            float2 p  = *(const float2*)&P_s[k * 32 + m0];
            float4 w  = *(const float4*)&W_s[k * 64 + 2 * m0];
            float2 ab = *(const float2*)&scal_s[k * 34 + 2 * es];
            unsigned long long p2 = pk2(p.x, p.y);
            unsigned long long wA = pk2(w.x, w.y), wB = pk2(w.z, w.w);
            unsigned long long aa = pk2(ab.x, ab.x), bb = pk2(ab.y, ab.y);
            fma2(lg0, p2, aa); fma2(lg1, p2, bb);
            fma2(g0A, wA, aa); fma2(g0B, wB, aa);
            fma2(g1A, wA, bb); fma2(g1B, wB, bb);
        }
        float2 l0 = upk2(lg0), l1 = upk2(lg1);
        float2 ga0 = upk2(g0A), gb0 = upk2(g0B);
        float2 ga1 = upk2(g1A), gb1 = upk2(g1B);

        float r0=0,r1=0,r2=0,r3=0,r4=0;   // m0:   den, env.xyzw
        float r5=0,r6=0,r7=0,r8=0,r9=0;   // m0+1
        int ei0 = es * 2, ei1 = ei0 + 1;
        int e0 = eids[ei0], e1 = eids[ei1];
        if (e0 >= 0) {
            float z0 = __expf(fminf(fmaxf(l0.x * 0.25f, -5.f), 5.f));
            float z1 = __expf(fminf(fmaxf(l0.y * 0.25f, -5.f), 5.f));
            float a0 = ga0.x + be0, a1 = ga0.y + be1, a2 = gb0.x + be2, a3 = gb0.y + be3;
            float s0 = a0 / (1.f + __expf(-a0)), s1 = a1 / (1.f + __expf(-a1));
            float s2 = a2 / (1.f + __expf(-a2)), s3 = a3 / (1.f + __expf(-a3));
            float4 q0 = ((const float4*)equiv)[(size_t)e0 * 32 + m0];
            float4 q1 = ((const float4*)equiv)[(size_t)e0 * 32 + m0 + 1];
            r0 += z0; r1 += z0*q0.x*s0; r2 += z0*q0.y*s1; r3 += z0*q0.z*s1; r4 += z0*q0.w*s1;
            r5 += z1; r6 += z1*q1.x*s2; r7 += z1*q1.y*s3; r8 += z1*q1.z*s3; r9 += z1*q1.w*s3;
        }
        if (e1 >= 0) {
            float z0 = __expf(fminf(fmaxf(l1.x * 0.25f, -5.f), 5.f));
            float z1 = __expf(fminf(fmaxf(l1.y * 0.25f, -5.f), 5.f));
            float a0 = ga1.x + be0, a1 = ga1.y + be1, a2 = gb1.x + be2, a3 = gb1.y + be3;
            float s0 = a0 / (1.f + __expf(-a0)), s1 = a1 / (1.f + __expf(-a1));
            float s2 = a2 / (1.f + __expf(-a2)), s3 = a3 / (1.f + __expf(-a3));
            float4 q0 = ((const float4*)equiv)[(size_t)e1 * 32 + m0];
            float4 q1 = ((const float4*)equiv)[(size_t)e1 * 32 + m0 + 1];
            r0 += z0; r1 += z0*q0.x*s0; r2 += z0*q0.y*s1; r3 += z0*q0.z*s1; r4 += z0*q0.w*s1;
            r5 += z1; r6 += z1*q1.x*s2; r7 += z1*q1.y*s3; r8 += z1*q1.z*s3; r9 += z1*q1.w*s3;
        }
#pragma unroll
        for (int o = 1; o <= 4; o <<= 1) {
            r0 += __shfl_xor_sync(0xffffffffu, r0, o);
            r1 += __shfl_xor_sync(0xffffffffu, r1, o);
            r2 += __shfl_xor_sync(0xffffffffu, r2, o);
            r3 += __shfl_xor_sync(0xffffffffu, r3, o);
            r4 += __shfl_xor_sync(0xffffffffu, r4, o);
            r5 += __shfl_xor_sync(0xffffffffu, r5, o);
            r6 += __shfl_xor_sync(0xffffffffu, r6, o);
            r7 += __shfl_xor_sync(0xffffffffu, r7, o);
            r8 += __shfl_xor_sync(0xffffffffu, r8, o);
            r9 += __shfl_xor_sync(0xffffffffu, r9, o);
        }
        if (es == 0) {
            acc_s[m0 * 8 + 0] += r0; acc_s[m0 * 8 + 1] += r1;
            acc_s[m0 * 8 + 2] += r2; acc_s[m0 * 8 + 3] += r3;
            acc_s[m0 * 8 + 4] += r4;
            acc_s[(m0 + 1) * 8 + 0] += r5; acc_s[(m0 + 1) * 8 + 1] += r6;
            acc_s[(m0 + 1) * 8 + 2] += r7; acc_s[(m0 + 1) * 8 + 3] += r8;
            acc_s[(m0 + 1) * 8 + 4] += r9;
        }
    }
    __syncthreads();

    if (tid < 32) {
        int m = tid;
        float den = acc_s[m * 8 + 0];
        float inv = den > 0.f ? 1.f / den : 0.f;
        float ax = acc_s[m * 8 + 1] * inv, ay = acc_s[m * 8 + 2] * inv;
        float az = acc_s[m * 8 + 3] * inv, aw = acc_s[m * 8 + 4] * inv;
        float s0 = ax * ax;
        float s1 = ay * ay + az * az + aw * aw;
#pragma unroll
        for (int o = 16; o; o >>= 1) {
            s0 += __shfl_xor_sync(0xffffffffu, s0, o);
            s1 += __shfl_xor_sync(0xffffffffu, s1, o);
        }
        float n0 = rsqrtf(s0 * (1.f / 32.f) + 1e-6f);
        float n1 = rsqrtf(s1 * (1.f / 96.f) + 1e-6f);
        *(float4*)&d_envnodes[(size_t)n * 128 + m * 4] =
            make_float4(ax * n0, ay * n1, az * n1, aw * n1);
    }
}

// ---------------- edge phase B: tensor product + TP layernorm + mix/sc GEMM + residual ----
// 512 threads, 64 edges per block. dyn smem (floats): sWc 20480 | sB 256 | sF 64*80 | sTp 64*32*8
__global__ __launch_bounds__(512, 1) void k_edgeB(
    const float* __restrict__ scal, const float* __restrict__ equiv,
    const float* __restrict__ cond, const float* __restrict__ ucoef,
    const float* __restrict__ W_mix, const float* __restrict__ b_mix,
    const float* __restrict__ W_sc,  const float* __restrict__ b_sc,
    const int* __restrict__ edge_center, const int* __restrict__ active,
    float* __restrict__ out)
{
    extern __shared__ float sm[];
    float* sWc = sm;                  // [80][256] combined (W_mix | W_sc)
    float* sB  = sWc + 20480;         // [256]
    float* sF  = sB + 256;            // [64][80] feats
    float* sTp = sF + 5120;           // [64][32][8] normalized tp_out

    int tid = threadIdx.x;
    long e0 = (long)blockIdx.x * 64;

    for (int idx = tid; idx < 20480; idx += 512) {
        int i = idx >> 8, j = idx & 255;
        sWc[idx] = (j < 128) ? W_mix[i * 128 + j] : W_sc[i * 128 + (j - 128)];
    }
    if (tid < 256) sB[tid] = (tid < 128) ? b_mix[tid] : b_sc[tid - 128];
    for (int idx = tid; idx < 64 * 16; idx += 512) {
        int el = idx >> 4, i = idx & 15;
        sF[el * 80 + 64 + i] = cond[(e0 + el) * 16 + i];
    }

    { // phase 2: tp_out + TP layernorm + feats (warp per edge, lane = m)
        int w = tid >> 5, m = tid & 31;
        for (int rep = 0; rep < 4; rep++) {
            int el = w * 4 + rep;
            long e = e0 + el;
            int nidx = edge_center[e];
            float4 x = *(const float4*)(equiv + e * 128 + m * 4);
            float4 y = *(const float4*)(d_envnodes + (size_t)nidx * 128 + m * 4);
            float t0 = x.x * y.x;
            float t1 = x.x * y.y, t2 = x.x * y.z, t3 = x.x * y.w;
            float t4 = x.y * y.x, t5 = x.z * y.x, t6 = x.w * y.x;
            float t7 = (x.y * y.y + x.z * y.z + x.w * y.w) * 0.5773502691896258f;
            float s0 = t0 * t0;
            float s1 = t1 * t1 + t2 * t2 + t3 * t3;
            float s2 = t4 * t4 + t5 * t5 + t6 * t6;
            float s3 = t7 * t7;
#pragma unroll
            for (int o = 16; o; o >>= 1) {
                s0 += __shfl_xor_sync(0xffffffffu, s0, o);
                s1 += __shfl_xor_sync(0xffffffffu, s1, o);
                s2 += __shfl_xor_sync(0xffffffffu, s2, o);
                s3 += __shfl_xor_sync(0xffffffffu, s3, o);
            }
            float r0 = rsqrtf(s0 * (1.f / 32.f) + 1e-6f);
            float r1 = rsqrtf(s1 * (1.f / 96.f) + 1e-6f);
            float r2 = rsqrtf(s2 * (1.f / 96.f) + 1e-6f);
            float r3 = rsqrtf(s3 * (1.f / 32.f) + 1e-6f);
            t0 *= r0; t1 *= r1; t2 *= r1; t3 *= r1;
            t4 *= r2; t5 *= r2; t6 *= r2; t7 *= r3;
            float* tp = &sTp[(el * 32 + m) * 8];
            tp[0] = t0; tp[1] = t1; tp[2] = t2; tp[3] = t3;
            tp[4] = t4; tp[5] = t5; tp[6] = t6; tp[7] = t7;
            sF[el * 80 + m]      = t0;
            sF[el * 80 + 32 + m] = t7;
        }
    }
    __syncthreads();

    // phase 3: F[64][80] @ Wc[80][256] with f32x2 packed FMAs.
    // thread = (tCol float4-column, tRow 8-edge group); k unrolled by 4 so f loads
    // become uniform LDS.128 per edge.
    int tCol = tid & 63, tRow = tid >> 6;
    float4 bias4 = ((float4*)sB)[tCol];
    unsigned long long accA[8], accB[8];
#pragma unroll
    for (int i = 0; i < 8; i++) {
        accA[i] = pk2(bias4.x, bias4.y);
        accB[i] = pk2(bias4.z, bias4.w);
    }
    for (int kb = 0; kb < 80; kb += 4) {
        float4 fv[8];
#pragma unroll
        for (int i = 0; i < 8; i++)
            fv[i] = *(const float4*)&sF[(tRow * 8 + i) * 80 + kb];
#pragma unroll
        for (int kk = 0; kk < 4; kk++) {
            float4 w4 = ((const float4*)(sWc + (kb + kk) * 256))[tCol];
            unsigned long long wA = pk2(w4.x, w4.y);
            unsigned long long wB = pk2(w4.z, w4.w);
#pragma unroll
            for (int i = 0; i < 8; i++) {
                float f = (kk == 0) ? fv[i].x : (kk == 1) ? fv[i].y
                        : (kk == 2) ? fv[i].z : fv[i].w;
                unsigned long long ff = pk2(f, f);
                fma2(accA[i], wA, ff);
                fma2(accB[i], wB, ff);
            }
        }
    }

    float u = ucoef[0];
    float c_old = rsqrtf(u * u + 1.f);
    float c_new = u * c_old;

#pragma unroll
    for (int i = 0; i < 8; i++) {
        int el = tRow * 8 + i;
        long e = e0 + el;
        long r = active[e];
        float2 axy = upk2(accA[i]);
        float2 azw = upk2(accB[i]);
        float4 a = make_float4(axy.x, axy.y, azw.x, azw.y);
        if (tCol < 32) {      // cols [0,128): mix[m][0..3], m == tCol
            int m2 = tCol;
            float* tp = &sTp[(el * 32 + m2) * 8];
            float4 ne;
            ne.x = a.x * tp[0] + a.y * tp[7];
            ne.y = a.z * tp[1] + a.w * tp[4];
            ne.z = a.z * tp[2] + a.w * tp[5];
            ne.w = a.z * tp[3] + a.w * tp[6];
            float4 b = *(const float4*)(equiv + r * 128 + m2 * 4);
            float4 o;
            o.x = c_old * b.x + c_new * ne.x;
            o.y = c_old * b.y + c_new * ne.y;
            o.z = c_old * b.z + c_new * ne.z;
            o.w = c_old * b.w + c_new * ne.w;
            *(float4*)(out + (long)E_CNT * 128 + r * 128 + m2 * 4) = o;
        } else {              // cols [128,256): new_scalar
            int jc = tCol - 32;
            float4 b = *(const float4*)(scal + r * 128 + jc * 4);
            float4 o;
            o.x = c_old * b.x + c_new * a.x;
            o.y = c_old * b.y + c_new * a.y;
            o.z = c_old * b.z + c_new * a.z;
            o.w = c_old * b.w + c_new * a.w;
            *(float4*)(out + r * 128 + jc * 4) = o;
        }
    }
}

// ---------------- launch ----------------
extern "C" void kernel_launch(void* const* d_in, const int* in_sizes, int n_in,
                              void* d_out, int out_size)
{
    const float* scal  = (const float*)d_in[0];
    const float* equiv = (const float*)d_in[1];
    const float* ninv  = (const float*)d_in[2];
    const float* cond  = (const float*)d_in[3];
    const float* ucoef = (const float*)d_in[4];
    const float* W_env = (const float*)d_in[5];
    const float* b_env = (const float*)d_in[6];
    const float* Wq    = (const float*)d_in[7];
    const float* Wk    = (const float*)d_in[8];
    const float* W_mix = (const float*)d_in[9];
    const float* b_mix = (const float*)d_in[10];
    const float* W_sc  = (const float*)d_in[11];
    const float* b_sc  = (const float*)d_in[12];
    const int*   ec    = (const int*)d_in[13];
    const int*   act   = (const int*)d_in[14];
    float* out = (float*)d_out;

    // CSR build
    k_zero<<<64, 256>>>();
    k_hist<<<E_CNT / 256, 256>>>(ec);
    k_scan<<<1, 1024>>>();
    k_scatter<<<E_CNT / 256, 256>>>(ec);

    // Q per node, then P factorization
    k_q<<<N_CNT, 512>>>(ninv, Wq);
    k_P<<<N_CNT / 32, 256>>>(Wk);

    // fused per-node attention/env
    const int SMEMA = (4096 + 8192 + 4352 + 256 + 16) * 4;
    cudaFuncSetAttribute(k_nodeA, cudaFuncAttributeMaxDynamicSharedMemorySize, SMEMA);
    k_nodeA<<<N_CNT, 128, SMEMA>>>(scal, equiv, W_env, b_env);

    // edge phase B
    const int SMEMB = (20480 + 256 + 5120 + 16384) * 4;
    cudaFuncSetAttribute(k_edgeB, cudaFuncAttributeMaxDynamicSharedMemorySize, SMEMB);
    k_edgeB<<<E_CNT / 64, 512, SMEMB>>>(scal, equiv, cond, ucoef,
                                        W_mix, b_mix, W_sc, b_sc, ec, act, out);
}

// round 5
// speedup vs baseline: 2.5903x; 1.0722x over previous
#include <cuda_runtime.h>
#include <math.h>

#define E_CNT 262144
#define N_CNT 16384

// ---------------- f32x2 packed-FMA helpers (bit-exact fp32) ----------------
__device__ __forceinline__ unsigned long long pk2(float lo, float hi) {
    unsigned long long r;
    asm("mov.b64 %0, {%1, %2};" : "=l"(r) : "f"(lo), "f"(hi));
    return r;
}
__device__ __forceinline__ void fma2(unsigned long long& d,
                                     unsigned long long a, unsigned long long b) {
    asm("fma.rn.f32x2 %0, %1, %2, %0;" : "+l"(d) : "l"(a), "l"(b));
}
__device__ __forceinline__ float2 upk2(unsigned long long v) {
    float2 f;
    asm("mov.b64 {%0, %1}, %2;" : "=f"(f.x), "=f"(f.y) : "l"(v));
    return f;
}

// ---------------- device scratch (static, allocation-free) ----------------
__device__ float d_P[(size_t)N_CNT * 4096];        // P[n][k][m]
__device__ float d_envnodes[N_CNT * 128];          // normalized env per node
__device__ int   d_cnt[N_CNT];                     // zeroed at load & by k_scatter
__device__ int   d_off[N_CNT + 1];
__device__ int   d_cur[N_CNT];
__device__ int   d_eid[E_CNT];

// ---------------- CSR build ----------------
__global__ void k_hist(const int* __restrict__ ec) {
    int e = blockIdx.x * blockDim.x + threadIdx.x;
    if (e < E_CNT) atomicAdd(&d_cnt[ec[e]], 1);
}
__global__ void k_scan() {
    __shared__ int part[1024];
    int t = threadIdx.x;
    int base = t * 16;
    int loc[16];
    int s = 0;
#pragma unroll
    for (int i = 0; i < 16; i++) { loc[i] = s; s += d_cnt[base + i]; }
    part[t] = s;
    __syncthreads();
    for (int o = 1; o < 1024; o <<= 1) {
        int v = (t >= o) ? part[t - o] : 0;
        __syncthreads();
        part[t] += v;
        __syncthreads();
    }
    int excl = (t > 0) ? part[t - 1] : 0;
#pragma unroll
    for (int i = 0; i < 16; i++) {
        d_off[base + i] = excl + loc[i];
        d_cur[base + i] = excl + loc[i];
    }
    if (t == 1023) d_off[N_CNT] = part[1023];
}
__global__ void k_scatter(const int* __restrict__ ec) {
    int e = blockIdx.x * blockDim.x + threadIdx.x;
    if (e < E_CNT) {
        int n = ec[e];
        int pos = atomicAdd(&d_cur[n], 1);
        d_eid[pos] = e;
        if (e < N_CNT) d_cnt[e] = 0;   // restore invariant for next call
    }
}

// ---------------- merged Q+P: 32 nodes per block ----------------
// Q[j][c] = sum_k ninv[j][k] * Wq[k][c]       (done in regs, exchanged via smem)
// P[n][k][m] = sum_d Wk[k][m*16+d] * Q[n][m*16+d]
// dyn smem: sQ 32*512 floats (64KB) | sB 8192 floats (32KB: ninv then Wk chunk)
__global__ __launch_bounds__(256, 2) void k_QP(
    const float* __restrict__ ninv, const float* __restrict__ Wq,
    const float* __restrict__ Wk)
{
    extern __shared__ float sm[];
    float* sQ = sm;            // [32][512]
    float* sB = sQ + 16384;    // scratch: ninv[32][64] then Wk chunk [16][512]
    int tid = threadIdx.x;
    int n0 = blockIdx.x * 32;

    { // load ninv 32x64 coalesced
        const float4* src = (const float4*)(ninv + (size_t)n0 * 64);
        float4* dst = (float4*)sB;
        for (int i = tid; i < 512; i += 256) dst[i] = src[i];
    }
    __syncthreads();

    // --- Q: thread owns columns (tid, tid+256) across all 32 nodes ---
    float acc0[32], acc1[32];
#pragma unroll
    for (int j = 0; j < 32; j++) { acc0[j] = 0.f; acc1[j] = 0.f; }
    for (int k = 0; k < 64; k++) {
        float w0 = Wq[k * 512 + tid];
        float w1 = Wq[k * 512 + tid + 256];
#pragma unroll
        for (int j = 0; j < 32; j++) {
            float nv = sB[j * 64 + k];   // broadcast
            acc0[j] += nv * w0;
            acc1[j] += nv * w1;
        }
    }
#pragma unroll
    for (int j = 0; j < 32; j++) {
        sQ[j * 512 + tid]       = acc0[j];
        sQ[j * 512 + tid + 256] = acc1[j];
    }
    __syncthreads();

    // --- P: thread (m, ns) covers 4 nodes, all k ---
    int m = tid & 31, ns = tid >> 5;
    float q[4][16];
#pragma unroll
    for (int j = 0; j < 4; j++) {
        const float4* Qp = (const float4*)(sQ + (ns * 4 + j) * 512 + m * 16);
#pragma unroll
        for (int v = 0; v < 4; v++) {
            float4 t = Qp[v];
            q[j][v * 4 + 0] = t.x; q[j][v * 4 + 1] = t.y;
            q[j][v * 4 + 2] = t.z; q[j][v * 4 + 3] = t.w;
        }
    }
    for (int kc = 0; kc < 128; kc += 16) {
        __syncthreads();
        {
            const float4* src = (const float4*)(Wk + (size_t)kc * 512);
            float4* dst = (float4*)sB;
            for (int i = tid; i < 2048; i += 256) dst[i] = src[i];
        }
        __syncthreads();
#pragma unroll
        for (int kk = 0; kk < 16; kk++) {
            const float* wr = &sB[kk * 512 + m * 16];
            float4 w0 = *(const float4*)(wr + 0);
            float4 w1 = *(const float4*)(wr + 4);
            float4 w2 = *(const float4*)(wr + 8);
            float4 w3 = *(const float4*)(wr + 12);
#pragma unroll
            for (int j = 0; j < 4; j++) {
                float acc = q[j][0] * w0.x + q[j][1] * w0.y + q[j][2] * w0.z + q[j][3] * w0.w
                          + q[j][4] * w1.x + q[j][5] * w1.y + q[j][6] * w1.z + q[j][7] * w1.w
                          + q[j][8] * w2.x + q[j][9] * w2.y + q[j][10] * w2.z + q[j][11] * w2.w
                          + q[j][12] * w3.x + q[j][13] * w3.y + q[j][14] * w3.z + q[j][15] * w3.w;
                int n = n0 + ns * 4 + j;
                d_P[(size_t)n * 4096 + (kc + kk) * 32 + m] = acc;
            }
        }
    }
}

// ---------------- per-node fused: gate + logits(P) + softmax + env agg + SO3 norm -----
__global__ __launch_bounds__(128, 3) void k_nodeA(
    const float* __restrict__ scal, const float* __restrict__ equiv,
    const float* __restrict__ W_env, const float* __restrict__ b_env)
{
    extern __shared__ float sm[];
    float* P_s    = sm;                 // [k][m] 4096
    float* W_s    = P_s + 4096;         // [k][64] 8192
    float* scal_s = W_s + 8192;         // [k][34]
    float* acc_s  = scal_s + 4352;      // [m][8]
    int*   eids   = (int*)(acc_s + 256);

    int n = blockIdx.x;
    int tid = threadIdx.x;
    int beg = d_off[n];
    int cnt = d_off[n + 1] - beg;

    {
        const float4* Pg = (const float4*)(d_P + (size_t)n * 4096);
        float4* Pd = (float4*)P_s;
        for (int i = tid; i < 1024; i += 128) Pd[i] = Pg[i];
        const float4* Wg = (const float4*)W_env;
        float4* Wd = (float4*)W_s;
        for (int i = tid; i < 2048; i += 128) Wd[i] = Wg[i];
        for (int i = tid; i < 256; i += 128) acc_s[i] = 0.f;
    }

    int mg = tid >> 3, es = tid & 7;
    int m0 = mg * 2;
    float be0 = b_env[2 * m0 + 0], be1 = b_env[2 * m0 + 1];
    float be2 = b_env[2 * m0 + 2], be3 = b_env[2 * m0 + 3];

    for (int base = 0; base < cnt; base += 16) {
        __syncthreads();
        if (tid < 16) {
            int idx = base + tid;
            eids[tid] = (idx < cnt) ? d_eid[beg + idx] : -1;
        }
        __syncthreads();
        for (int i = tid; i < 512; i += 128) {
            int el = i >> 5, c = i & 31;
            int e = eids[el];
            float4 v = make_float4(0.f, 0.f, 0.f, 0.f);
            if (e >= 0) v = ((const float4*)scal)[(size_t)e * 32 + c];
            scal_s[(4 * c + 0) * 34 + el] = v.x;
            scal_s[(4 * c + 1) * 34 + el] = v.y;
            scal_s[(4 * c + 2) * 34 + el] = v.z;
            scal_s[(4 * c + 3) * 34 + el] = v.w;
        }
        __syncthreads();

        unsigned long long lg0 = 0ull, lg1 = 0ull;
        unsigned long long g0A = 0ull, g0B = 0ull;
        unsigned long long g1A = 0ull, g1B = 0ull;
#pragma unroll 4
        for (int k = 0; k < 128; k++) {
            float2 p  = *(const float2*)&P_s[k * 32 + m0];
            float4 w  = *(const float4*)&W_s[k * 64 + 2 * m0];
            float2 ab = *(const float2*)&scal_s[k * 34 + 2 * es];
            unsigned long long p2 = pk2(p.x, p.y);
            unsigned long long wA = pk2(w.x, w.y), wB = pk2(w.z, w.w);
            unsigned long long aa = pk2(ab.x, ab.x), bb = pk2(ab.y, ab.y);
            fma2(lg0, p2, aa); fma2(lg1, p2, bb);
            fma2(g0A, wA, aa); fma2(g0B, wB, aa);
            fma2(g1A, wA, bb); fma2(g1B, wB, bb);
        }
        float2 l0 = upk2(lg0), l1 = upk2(lg1);
        float2 ga0 = upk2(g0A), gb0 = upk2(g0B);
        float2 ga1 = upk2(g1A), gb1 = upk2(g1B);

        float r0=0,r1=0,r2=0,r3=0,r4=0;
        float r5=0,r6=0,r7=0,r8=0,r9=0;
        int ei0 = es * 2, ei1 = ei0 + 1;
        int e0 = eids[ei0], e1 = eids[ei1];
        if (e0 >= 0) {
            float z0 = __expf(fminf(fmaxf(l0.x * 0.25f, -5.f), 5.f));
            float z1 = __expf(fminf(fmaxf(l0.y * 0.25f, -5.f), 5.f));
            float a0 = ga0.x + be0, a1 = ga0.y + be1, a2 = gb0.x + be2, a3 = gb0.y + be3;
            float s0 = a0 / (1.f + __expf(-a0)), s1 = a1 / (1.f + __expf(-a1));
            float s2 = a2 / (1.f + __expf(-a2)), s3 = a3 / (1.f + __expf(-a3));
            float4 q0 = ((const float4*)equiv)[(size_t)e0 * 32 + m0];
            float4 q1 = ((const float4*)equiv)[(size_t)e0 * 32 + m0 + 1];
            r0 += z0; r1 += z0*q0.x*s0; r2 += z0*q0.y*s1; r3 += z0*q0.z*s1; r4 += z0*q0.w*s1;
            r5 += z1; r6 += z1*q1.x*s2; r7 += z1*q1.y*s3; r8 += z1*q1.z*s3; r9 += z1*q1.w*s3;
        }
        if (e1 >= 0) {
            float z0 = __expf(fminf(fmaxf(l1.x * 0.25f, -5.f), 5.f));
            float z1 = __expf(fminf(fmaxf(l1.y * 0.25f, -5.f), 5.f));
            float a0 = ga1.x + be0, a1 = ga1.y + be1, a2 = gb1.x + be2, a3 = gb1.y + be3;
            float s0 = a0 / (1.f + __expf(-a0)), s1 = a1 / (1.f + __expf(-a1));
            float s2 = a2 / (1.f + __expf(-a2)), s3 = a3 / (1.f + __expf(-a3));
            float4 q0 = ((const float4*)equiv)[(size_t)e1 * 32 + m0];
            float4 q1 = ((const float4*)equiv)[(size_t)e1 * 32 + m0 + 1];
            r0 += z0; r1 += z0*q0.x*s0; r2 += z0*q0.y*s1; r3 += z0*q0.z*s1; r4 += z0*q0.w*s1;
            r5 += z1; r6 += z1*q1.x*s2; r7 += z1*q1.y*s3; r8 += z1*q1.z*s3; r9 += z1*q1.w*s3;
        }
#pragma unroll
        for (int o = 1; o <= 4; o <<= 1) {
            r0 += __shfl_xor_sync(0xffffffffu, r0, o);
            r1 += __shfl_xor_sync(0xffffffffu, r1, o);
            r2 += __shfl_xor_sync(0xffffffffu, r2, o);
            r3 += __shfl_xor_sync(0xffffffffu, r3, o);
            r4 += __shfl_xor_sync(0xffffffffu, r4, o);
            r5 += __shfl_xor_sync(0xffffffffu, r5, o);
            r6 += __shfl_xor_sync(0xffffffffu, r6, o);
            r7 += __shfl_xor_sync(0xffffffffu, r7, o);
            r8 += __shfl_xor_sync(0xffffffffu, r8, o);
            r9 += __shfl_xor_sync(0xffffffffu, r9, o);
        }
        if (es == 0) {
            acc_s[m0 * 8 + 0] += r0; acc_s[m0 * 8 + 1] += r1;
            acc_s[m0 * 8 + 2] += r2; acc_s[m0 * 8 + 3] += r3;
            acc_s[m0 * 8 + 4] += r4;
            acc_s[(m0 + 1) * 8 + 0] += r5; acc_s[(m0 + 1) * 8 + 1] += r6;
            acc_s[(m0 + 1) * 8 + 2] += r7; acc_s[(m0 + 1) * 8 + 3] += r8;
            acc_s[(m0 + 1) * 8 + 4] += r9;
        }
    }
    __syncthreads();

    if (tid < 32) {
        int m = tid;
        float den = acc_s[m * 8 + 0];
        float inv = den > 0.f ? 1.f / den : 0.f;
        float ax = acc_s[m * 8 + 1] * inv, ay = acc_s[m * 8 + 2] * inv;
        float az = acc_s[m * 8 + 3] * inv, aw = acc_s[m * 8 + 4] * inv;
        float s0 = ax * ax;
        float s1 = ay * ay + az * az + aw * aw;
#pragma unroll
        for (int o = 16; o; o >>= 1) {
            s0 += __shfl_xor_sync(0xffffffffu, s0, o);
            s1 += __shfl_xor_sync(0xffffffffu, s1, o);
        }
        float n0 = rsqrtf(s0 * (1.f / 32.f) + 1e-6f);
        float n1 = rsqrtf(s1 * (1.f / 96.f) + 1e-6f);
        *(float4*)&d_envnodes[(size_t)n * 128 + m * 4] =
            make_float4(ax * n0, ay * n1, az * n1, aw * n1);
    }
}

// ---------------- edge phase B: PERSISTENT. weights loaded once per SM ----------------
__global__ __launch_bounds__(512, 1) void k_edgeB(
    const float* __restrict__ scal, const float* __restrict__ equiv,
    const float* __restrict__ cond, const float* __restrict__ ucoef,
    const float* __restrict__ W_mix, const float* __restrict__ b_mix,
    const float* __restrict__ W_sc,  const float* __restrict__ b_sc,
    const int* __restrict__ edge_center, const int* __restrict__ active,
    float* __restrict__ out)
{
    extern __shared__ float sm[];
    float* sWc = sm;                  // [80][256]
    float* sB  = sWc + 20480;         // [256]
    float* sF  = sB + 256;            // [64][80]
    float* sTp = sF + 5120;           // [64][32][8]

    int tid = threadIdx.x;

    for (int idx = tid; idx < 20480; idx += 512) {
        int i = idx >> 8, j = idx & 255;
        sWc[idx] = (j < 128) ? W_mix[i * 128 + j] : W_sc[i * 128 + (j - 128)];
    }
    if (tid < 256) sB[tid] = (tid < 128) ? b_mix[tid] : b_sc[tid - 128];

    float u = ucoef[0];
    float c_old = rsqrtf(u * u + 1.f);
    float c_new = u * c_old;

    int tCol = tid & 63, tRow = tid >> 6;
    int w = tid >> 5, m = tid & 31;

    for (int tile = blockIdx.x; tile < E_CNT / 64; tile += gridDim.x) {
        __syncthreads();   // protects sF/sTp reuse + first-iter weight fill
        long e0 = (long)tile * 64;

        for (int idx = tid; idx < 64 * 16; idx += 512) {
            int el = idx >> 4, i = idx & 15;
            sF[el * 80 + 64 + i] = cond[(e0 + el) * 16 + i];
        }

        { // tensor product + TP layernorm + feats
            for (int rep = 0; rep < 4; rep++) {
                int el = w * 4 + rep;
                long e = e0 + el;
                int nidx = edge_center[e];
                float4 x = *(const float4*)(equiv + e * 128 + m * 4);
                float4 y = *(const float4*)(d_envnodes + (size_t)nidx * 128 + m * 4);
                float t0 = x.x * y.x;
                float t1 = x.x * y.y, t2 = x.x * y.z, t3 = x.x * y.w;
                float t4 = x.y * y.x, t5 = x.z * y.x, t6 = x.w * y.x;
                float t7 = (x.y * y.y + x.z * y.z + x.w * y.w) * 0.5773502691896258f;
                float s0 = t0 * t0;
                float s1 = t1 * t1 + t2 * t2 + t3 * t3;
                float s2 = t4 * t4 + t5 * t5 + t6 * t6;
                float s3 = t7 * t7;
#pragma unroll
                for (int o = 16; o; o >>= 1) {
                    s0 += __shfl_xor_sync(0xffffffffu, s0, o);
                    s1 += __shfl_xor_sync(0xffffffffu, s1, o);
                    s2 += __shfl_xor_sync(0xffffffffu, s2, o);
                    s3 += __shfl_xor_sync(0xffffffffu, s3, o);
                }
                float r0 = rsqrtf(s0 * (1.f / 32.f) + 1e-6f);
                float r1 = rsqrtf(s1 * (1.f / 96.f) + 1e-6f);
                float r2 = rsqrtf(s2 * (1.f / 96.f) + 1e-6f);
                float r3 = rsqrtf(s3 * (1.f / 32.f) + 1e-6f);
                t0 *= r0; t1 *= r1; t2 *= r1; t3 *= r1;
                t4 *= r2; t5 *= r2; t6 *= r2; t7 *= r3;
                float* tp = &sTp[(el * 32 + m) * 8];
                tp[0] = t0; tp[1] = t1; tp[2] = t2; tp[3] = t3;
                tp[4] = t4; tp[5] = t5; tp[6] = t6; tp[7] = t7;
                sF[el * 80 + m]      = t0;
                sF[el * 80 + 32 + m] = t7;
            }
        }
        __syncthreads();

        // F[64][80] @ Wc[80][256], f32x2 packed
        float4 bias4 = ((float4*)sB)[tCol];
        unsigned long long accA[8], accB[8];
#pragma unroll
        for (int i = 0; i < 8; i++) {
            accA[i] = pk2(bias4.x, bias4.y);
            accB[i] = pk2(bias4.z, bias4.w);
        }
        for (int kb = 0; kb < 80; kb += 4) {
            float4 fv[8];
#pragma unroll
            for (int i = 0; i < 8; i++)
                fv[i] = *(const float4*)&sF[(tRow * 8 + i) * 80 + kb];
#pragma unroll
            for (int kk = 0; kk < 4; kk++) {
                float4 w4 = ((const float4*)(sWc + (kb + kk) * 256))[tCol];
                unsigned long long wA = pk2(w4.x, w4.y);
                unsigned long long wB = pk2(w4.z, w4.w);
#pragma unroll
                for (int i = 0; i < 8; i++) {
                    float f = (kk == 0) ? fv[i].x : (kk == 1) ? fv[i].y
                            : (kk == 2) ? fv[i].z : fv[i].w;
                    unsigned long long ff = pk2(f, f);
                    fma2(accA[i], wA, ff);
                    fma2(accB[i], wB, ff);
                }
            }
        }

#pragma unroll
        for (int i = 0; i < 8; i++) {
            int el = tRow * 8 + i;
            long e = e0 + el;
            long r = active[e];
            float2 axy = upk2(accA[i]);
            float2 azw = upk2(accB[i]);
            float4 a = make_float4(axy.x, axy.y, azw.x, azw.y);
            if (tCol < 32) {
                int m2 = tCol;
                float* tp = &sTp[(el * 32 + m2) * 8];
                float4 ne;
                ne.x = a.x * tp[0] + a.y * tp[7];
                ne.y = a.z * tp[1] + a.w * tp[4];
                ne.z = a.z * tp[2] + a.w * tp[5];
                ne.w = a.z * tp[3] + a.w * tp[6];
                float4 b = *(const float4*)(equiv + r * 128 + m2 * 4);
                float4 o;
                o.x = c_old * b.x + c_new * ne.x;
                o.y = c_old * b.y + c_new * ne.y;
                o.z = c_old * b.z + c_new * ne.z;
                o.w = c_old * b.w + c_new * ne.w;
                *(float4*)(out + (long)E_CNT * 128 + r * 128 + m2 * 4) = o;
            } else {
                int jc = tCol - 32;
                float4 b = *(const float4*)(scal + r * 128 + jc * 4);
                float4 o;
                o.x = c_old * b.x + c_new * a.x;
                o.y = c_old * b.y + c_new * a.y;
                o.z = c_old * b.z + c_new * a.z;
                o.w = c_old * b.w + c_new * a.w;
                *(float4*)(out + r * 128 + jc * 4) = o;
            }
        }
    }
}

// ---------------- launch ----------------
extern "C" void kernel_launch(void* const* d_in, const int* in_sizes, int n_in,
                              void* d_out, int out_size)
{
    const float* scal  = (const float*)d_in[0];
    const float* equiv = (const float*)d_in[1];
    const float* ninv  = (const float*)d_in[2];
    const float* cond  = (const float*)d_in[3];
    const float* ucoef = (const float*)d_in[4];
    const float* W_env = (const float*)d_in[5];
    const float* b_env = (const float*)d_in[6];
    const float* Wq    = (const float*)d_in[7];
    const float* Wk    = (const float*)d_in[8];
    const float* W_mix = (const float*)d_in[9];
    const float* b_mix = (const float*)d_in[10];
    const float* W_sc  = (const float*)d_in[11];
    const float* b_sc  = (const float*)d_in[12];
    const int*   ec    = (const int*)d_in[13];
    const int*   act   = (const int*)d_in[14];
    float* out = (float*)d_out;

    // launch order chosen so the profiled launch (ours #3, 0-based) is k_QP
    k_hist<<<E_CNT / 256, 256>>>(ec);          // 0
    k_scan<<<1, 1024>>>();                     // 1
    k_scatter<<<E_CNT / 256, 256>>>(ec);       // 2

    const int SMEMQP = (16384 + 8192) * 4;
    cudaFuncSetAttribute(k_QP, cudaFuncAttributeMaxDynamicSharedMemorySize, SMEMQP);
    k_QP<<<N_CNT / 32, 256, SMEMQP>>>(ninv, Wq, Wk);   // 3  <- profiled

    const int SMEMA = (4096 + 8192 + 4352 + 256 + 16) * 4;
    cudaFuncSetAttribute(k_nodeA, cudaFuncAttributeMaxDynamicSharedMemorySize, SMEMA);
    k_nodeA<<<N_CNT, 128, SMEMA>>>(scal, equiv, W_env, b_env);   // 4

    const int SMEMB = (20480 + 256 + 5120 + 16384) * 4;
    cudaFuncSetAttribute(k_edgeB, cudaFuncAttributeMaxDynamicSharedMemorySize, SMEMB);
    k_edgeB<<<148, 512, SMEMB>>>(scal, equiv, cond, ucoef,
                                 W_mix, b_mix, W_sc, b_sc, ec, act, out);  // 5
}

// round 6
// speedup vs baseline: 3.0751x; 1.1871x over previous
#include <cuda_runtime.h>
#include <math.h>

#define E_CNT 262144
#define N_CNT 16384

// XOR swizzle within a 128-float4 (512-float) row: kills 4-way LDS conflicts
#define SW4(f) ((f) ^ (((f) >> 3) & 7))

// ---------------- f32x2 packed-FMA helpers (bit-exact fp32) ----------------
__device__ __forceinline__ unsigned long long pk2(float lo, float hi) {
    unsigned long long r;
    asm("mov.b64 %0, {%1, %2};" : "=l"(r) : "f"(lo), "f"(hi));
    return r;
}
__device__ __forceinline__ void fma2(unsigned long long& d,
                                     unsigned long long a, unsigned long long b) {
    asm("fma.rn.f32x2 %0, %1, %2, %0;" : "+l"(d) : "l"(a), "l"(b));
}
__device__ __forceinline__ float2 upk2(unsigned long long v) {
    float2 f;
    asm("mov.b64 {%0, %1}, %2;" : "=f"(f.x), "=f"(f.y) : "l"(v));
    return f;
}

// ---------------- device scratch (static, allocation-free) ----------------
__device__ float d_P[(size_t)N_CNT * 4096];        // P[n][k][m]
__device__ float d_envnodes[N_CNT * 128];          // normalized env per node
__device__ int   d_cnt[N_CNT];                     // zero at load & restored by k_scatter
__device__ int   d_off[N_CNT + 1];
__device__ int   d_cur[N_CNT];
__device__ int   d_eid[E_CNT];

// ---------------- CSR scan / scatter ----------------
__global__ void k_scan() {
    __shared__ int part[1024];
    int t = threadIdx.x;
    int base = t * 16;
    int loc[16];
    int s = 0;
#pragma unroll
    for (int i = 0; i < 16; i++) { loc[i] = s; s += d_cnt[base + i]; }
    part[t] = s;
    __syncthreads();
    for (int o = 1; o < 1024; o <<= 1) {
        int v = (t >= o) ? part[t - o] : 0;
        __syncthreads();
        part[t] += v;
        __syncthreads();
    }
    int excl = (t > 0) ? part[t - 1] : 0;
#pragma unroll
    for (int i = 0; i < 16; i++) {
        d_off[base + i] = excl + loc[i];
        d_cur[base + i] = excl + loc[i];
    }
    if (t == 1023) d_off[N_CNT] = part[1023];
}
__global__ void k_scatter(const int* __restrict__ ec) {
    int e = blockIdx.x * blockDim.x + threadIdx.x;
    if (e < E_CNT) {
        int n = ec[e];
        int pos = atomicAdd(&d_cur[n], 1);
        d_eid[pos] = e;
        if (e < N_CNT) d_cnt[e] = 0;   // restore invariant for next call
    }
}

// ---------------- merged Q+P (+ edge histogram): 32 nodes per block ----------------
// dyn smem: sQ 32*512 floats (64KB) | sB 8192 floats (32KB: ninv then Wk chunk, swizzled)
__global__ __launch_bounds__(256, 2) void k_QP(
    const float* __restrict__ ninv, const float* __restrict__ Wq,
    const float* __restrict__ Wk,   const int* __restrict__ ec)
{
    extern __shared__ float sm[];
    float* sQ = sm;            // [32][512]
    float* sB = sQ + 16384;    // scratch
    int tid = threadIdx.x;
    int n0 = blockIdx.x * 32;

    { // fused histogram: 512 edges per block
        int e = blockIdx.x * 512 + tid;
        atomicAdd(&d_cnt[ec[e]], 1);
        atomicAdd(&d_cnt[ec[e + 256]], 1);
    }

    { // load ninv 32x64 coalesced
        const float4* src = (const float4*)(ninv + (size_t)n0 * 64);
        float4* dst = (float4*)sB;
        for (int i = tid; i < 512; i += 256) dst[i] = src[i];
    }
    __syncthreads();

    // --- Q: thread owns columns (tid, tid+256) across all 32 nodes ---
    float acc0[32], acc1[32];
#pragma unroll
    for (int j = 0; j < 32; j++) { acc0[j] = 0.f; acc1[j] = 0.f; }
    for (int k = 0; k < 64; k++) {
        float w0 = Wq[k * 512 + tid];
        float w1 = Wq[k * 512 + tid + 256];
#pragma unroll
        for (int j = 0; j < 32; j++) {
            float nv = sB[j * 64 + k];   // broadcast
            acc0[j] += nv * w0;
            acc1[j] += nv * w1;
        }
    }
#pragma unroll
    for (int j = 0; j < 32; j++) {
        sQ[j * 512 + tid]       = acc0[j];
        sQ[j * 512 + tid + 256] = acc1[j];
    }
    __syncthreads();

    // --- P: thread (m, ns) covers 4 nodes, all k ---
    int m = tid & 31, ns = tid >> 5;
    float q[4][16];
#pragma unroll
    for (int j = 0; j < 4; j++) {
        const float4* Qp = (const float4*)(sQ + (ns * 4 + j) * 512 + m * 16);
#pragma unroll
        for (int v = 0; v < 4; v++) {
            float4 t = Qp[v];
            q[j][v * 4 + 0] = t.x; q[j][v * 4 + 1] = t.y;
            q[j][v * 4 + 2] = t.z; q[j][v * 4 + 3] = t.w;
        }
    }
    int f0 = m * 4;
    int cxor = (m >> 1) & 7;
    for (int kc = 0; kc < 128; kc += 16) {
        __syncthreads();
        { // stage Wk chunk with XOR swizzle (conflict-free LDS.128 reads below)
            const float4* src = (const float4*)(Wk + (size_t)kc * 512);
            float4* dst = (float4*)sB;
            for (int i = tid; i < 2048; i += 256) {
                int row = i >> 7, f = i & 127;
                dst[row * 128 + SW4(f)] = src[i];
            }
        }
        __syncthreads();
#pragma unroll
        for (int kk = 0; kk < 16; kk++) {
            const float4* row4 = (const float4*)sB + kk * 128;
            float4 w0 = row4[(f0 + 0) ^ cxor];
            float4 w1 = row4[(f0 + 1) ^ cxor];
            float4 w2 = row4[(f0 + 2) ^ cxor];
            float4 w3 = row4[(f0 + 3) ^ cxor];
#pragma unroll
            for (int j = 0; j < 4; j++) {
                float acc = q[j][0] * w0.x + q[j][1] * w0.y + q[j][2] * w0.z + q[j][3] * w0.w
                          + q[j][4] * w1.x + q[j][5] * w1.y + q[j][6] * w1.z + q[j][7] * w1.w
                          + q[j][8] * w2.x + q[j][9] * w2.y + q[j][10] * w2.z + q[j][11] * w2.w
                          + q[j][12] * w3.x + q[j][13] * w3.y + q[j][14] * w3.z + q[j][15] * w3.w;
                int n = n0 + ns * 4 + j;
                d_P[(size_t)n * 4096 + (kc + kk) * 32 + m] = acc;
            }
        }
    }
}

// ---------------- per-node fused, PERSISTENT: W_env loaded once per block -------
__global__ __launch_bounds__(128, 3) void k_nodeA(
    const float* __restrict__ scal, const float* __restrict__ equiv,
    const float* __restrict__ W_env, const float* __restrict__ b_env)
{
    extern __shared__ float sm[];
    float* P_s    = sm;                 // [k][m] 4096
    float* W_s    = P_s + 4096;         // [k][64] 8192
    float* scal_s = W_s + 8192;         // [k][34]
    float* acc_s  = scal_s + 4352;      // [m][8]
    int*   eids   = (int*)(acc_s + 256);

    int tid = threadIdx.x;
    int mg = tid >> 3, es = tid & 7;
    int m0 = mg * 2;

    { // W_env once per block (persistent)
        const float4* Wg = (const float4*)W_env;
        float4* Wd = (float4*)W_s;
        for (int i = tid; i < 2048; i += 128) Wd[i] = Wg[i];
    }
    float be0 = b_env[2 * m0 + 0], be1 = b_env[2 * m0 + 1];
    float be2 = b_env[2 * m0 + 2], be3 = b_env[2 * m0 + 3];

    for (int n = blockIdx.x; n < N_CNT; n += gridDim.x) {
        __syncthreads();   // prior node fully done (epilogue read acc_s)
        int beg = d_off[n];
        int cnt = d_off[n + 1] - beg;
        {
            const float4* Pg = (const float4*)(d_P + (size_t)n * 4096);
            float4* Pd = (float4*)P_s;
            for (int i = tid; i < 1024; i += 128) Pd[i] = Pg[i];
            for (int i = tid; i < 256; i += 128) acc_s[i] = 0.f;
        }

        for (int base = 0; base < cnt; base += 16) {
            __syncthreads();
            if (tid < 16) {
                int idx = base + tid;
                eids[tid] = (idx < cnt) ? d_eid[beg + idx] : -1;
            }
            __syncthreads();
            for (int i = tid; i < 512; i += 128) {
                int el = i >> 5, c = i & 31;
                int e = eids[el];
                float4 v = make_float4(0.f, 0.f, 0.f, 0.f);
                if (e >= 0) v = ((const float4*)scal)[(size_t)e * 32 + c];
                scal_s[(4 * c + 0) * 34 + el] = v.x;
                scal_s[(4 * c + 1) * 34 + el] = v.y;
                scal_s[(4 * c + 2) * 34 + el] = v.z;
                scal_s[(4 * c + 3) * 34 + el] = v.w;
            }
            __syncthreads();

            unsigned long long lg0 = 0ull, lg1 = 0ull;
            unsigned long long g0A = 0ull, g0B = 0ull;
            unsigned long long g1A = 0ull, g1B = 0ull;
#pragma unroll 4
            for (int k = 0; k < 128; k++) {
                float2 p  = *(const float2*)&P_s[k * 32 + m0];
                float4 w  = *(const float4*)&W_s[k * 64 + 2 * m0];
                float2 ab = *(const float2*)&scal_s[k * 34 + 2 * es];
                unsigned long long p2 = pk2(p.x, p.y);
                unsigned long long wA = pk2(w.x, w.y), wB = pk2(w.z, w.w);
                unsigned long long aa = pk2(ab.x, ab.x), bb = pk2(ab.y, ab.y);
                fma2(lg0, p2, aa); fma2(lg1, p2, bb);
                fma2(g0A, wA, aa); fma2(g0B, wB, aa);
                fma2(g1A, wA, bb); fma2(g1B, wB, bb);
            }
            float2 l0 = upk2(lg0), l1 = upk2(lg1);
            float2 ga0 = upk2(g0A), gb0 = upk2(g0B);
            float2 ga1 = upk2(g1A), gb1 = upk2(g1B);

            float r0=0,r1=0,r2=0,r3=0,r4=0;
            float r5=0,r6=0,r7=0,r8=0,r9=0;
            int ei0 = es * 2, ei1 = ei0 + 1;
            int e0 = eids[ei0], e1 = eids[ei1];
            if (e0 >= 0) {
                float z0 = __expf(fminf(fmaxf(l0.x * 0.25f, -5.f), 5.f));
                float z1 = __expf(fminf(fmaxf(l0.y * 0.25f, -5.f), 5.f));
                float a0 = ga0.x + be0, a1 = ga0.y + be1, a2 = gb0.x + be2, a3 = gb0.y + be3;
                float s0 = a0 / (1.f + __expf(-a0)), s1 = a1 / (1.f + __expf(-a1));
                float s2 = a2 / (1.f + __expf(-a2)), s3 = a3 / (1.f + __expf(-a3));
                float4 q0 = ((const float4*)equiv)[(size_t)e0 * 32 + m0];
                float4 q1 = ((const float4*)equiv)[(size_t)e0 * 32 + m0 + 1];
                r0 += z0; r1 += z0*q0.x*s0; r2 += z0*q0.y*s1; r3 += z0*q0.z*s1; r4 += z0*q0.w*s1;
                r5 += z1; r6 += z1*q1.x*s2; r7 += z1*q1.y*s3; r8 += z1*q1.z*s3; r9 += z1*q1.w*s3;
            }
            if (e1 >= 0) {
                float z0 = __expf(fminf(fmaxf(l1.x * 0.25f, -5.f), 5.f));
                float z1 = __expf(fminf(fmaxf(l1.y * 0.25f, -5.f), 5.f));
                float a0 = ga1.x + be0, a1 = ga1.y + be1, a2 = gb1.x + be2, a3 = gb1.y + be3;
                float s0 = a0 / (1.f + __expf(-a0)), s1 = a1 / (1.f + __expf(-a1));
                float s2 = a2 / (1.f + __expf(-a2)), s3 = a3 / (1.f + __expf(-a3));
                float4 q0 = ((const float4*)equiv)[(size_t)e1 * 32 + m0];
                float4 q1 = ((const float4*)equiv)[(size_t)e1 * 32 + m0 + 1];
                r0 += z0; r1 += z0*q0.x*s0; r2 += z0*q0.y*s1; r3 += z0*q0.z*s1; r4 += z0*q0.w*s1;
                r5 += z1; r6 += z1*q1.x*s2; r7 += z1*q1.y*s3; r8 += z1*q1.z*s3; r9 += z1*q1.w*s3;
            }
#pragma unroll
            for (int o = 1; o <= 4; o <<= 1) {
                r0 += __shfl_xor_sync(0xffffffffu, r0, o);
                r1 += __shfl_xor_sync(0xffffffffu, r1, o);
                r2 += __shfl_xor_sync(0xffffffffu, r2, o);
                r3 += __shfl_xor_sync(0xffffffffu, r3, o);
                r4 += __shfl_xor_sync(0xffffffffu, r4, o);
                r5 += __shfl_xor_sync(0xffffffffu, r5, o);
                r6 += __shfl_xor_sync(0xffffffffu, r6, o);
                r7 += __shfl_xor_sync(0xffffffffu, r7, o);
                r8 += __shfl_xor_sync(0xffffffffu, r8, o);
                r9 += __shfl_xor_sync(0xffffffffu, r9, o);
            }
            if (es == 0) {
                acc_s[m0 * 8 + 0] += r0; acc_s[m0 * 8 + 1] += r1;
                acc_s[m0 * 8 + 2] += r2; acc_s[m0 * 8 + 3] += r3;
                acc_s[m0 * 8 + 4] += r4;
                acc_s[(m0 + 1) * 8 + 0] += r5; acc_s[(m0 + 1) * 8 + 1] += r6;
                acc_s[(m0 + 1) * 8 + 2] += r7; acc_s[(m0 + 1) * 8 + 3] += r8;
                acc_s[(m0 + 1) * 8 + 4] += r9;
            }
        }
        __syncthreads();

        if (tid < 32) {
            int m = tid;
            float den = acc_s[m * 8 + 0];
            float inv = den > 0.f ? 1.f / den : 0.f;
            float ax = acc_s[m * 8 + 1] * inv, ay = acc_s[m * 8 + 2] * inv;
            float az = acc_s[m * 8 + 3] * inv, aw = acc_s[m * 8 + 4] * inv;
            float s0 = ax * ax;
            float s1 = ay * ay + az * az + aw * aw;
#pragma unroll
            for (int o = 16; o; o >>= 1) {
                s0 += __shfl_xor_sync(0xffffffffu, s0, o);
                s1 += __shfl_xor_sync(0xffffffffu, s1, o);
            }
            float n0 = rsqrtf(s0 * (1.f / 32.f) + 1e-6f);
            float n1 = rsqrtf(s1 * (1.f / 96.f) + 1e-6f);
            *(float4*)&d_envnodes[(size_t)n * 128 + m * 4] =
                make_float4(ax * n0, ay * n1, az * n1, aw * n1);
        }
    }
}

// ---------------- edge phase B: PERSISTENT ----------------
__global__ __launch_bounds__(512, 1) void k_edgeB(
    const float* __restrict__ scal, const float* __restrict__ equiv,
    const float* __restrict__ cond, const float* __restrict__ ucoef,
    const float* __restrict__ W_mix, const float* __restrict__ b_mix,
    const float* __restrict__ W_sc,  const float* __restrict__ b_sc,
    const int* __restrict__ edge_center, const int* __restrict__ active,
    float* __restrict__ out)
{
    extern __shared__ float sm[];
    float* sWc = sm;                  // [80][256]
    float* sB  = sWc + 20480;         // [256]
    float* sF  = sB + 256;            // [64][80]
    float* sTp = sF + 5120;           // [64][32][8]

    int tid = threadIdx.x;

    for (int idx = tid; idx < 20480; idx += 512) {
        int i = idx >> 8, j = idx & 255;
        sWc[idx] = (j < 128) ? W_mix[i * 128 + j] : W_sc[i * 128 + (j - 128)];
    }
    if (tid < 256) sB[tid] = (tid < 128) ? b_mix[tid] : b_sc[tid - 128];

    float u = ucoef[0];
    float c_old = rsqrtf(u * u + 1.f);
    float c_new = u * c_old;

    int tCol = tid & 63, tRow = tid >> 6;
    int w = tid >> 5, m = tid & 31;

    for (int tile = blockIdx.x; tile < E_CNT / 64; tile += gridDim.x) {
        __syncthreads();
        long e0 = (long)tile * 64;

        for (int idx = tid; idx < 64 * 16; idx += 512) {
            int el = idx >> 4, i = idx & 15;
            sF[el * 80 + 64 + i] = cond[(e0 + el) * 16 + i];
        }

        { // tensor product + TP layernorm + feats
            for (int rep = 0; rep < 4; rep++) {
                int el = w * 4 + rep;
                long e = e0 + el;
                int nidx = edge_center[e];
                float4 x = *(const float4*)(equiv + e * 128 + m * 4);
                float4 y = *(const float4*)(d_envnodes + (size_t)nidx * 128 + m * 4);
                float t0 = x.x * y.x;
                float t1 = x.x * y.y, t2 = x.x * y.z, t3 = x.x * y.w;
                float t4 = x.y * y.x, t5 = x.z * y.x, t6 = x.w * y.x;
                float t7 = (x.y * y.y + x.z * y.z + x.w * y.w) * 0.5773502691896258f;
                float s0 = t0 * t0;
                float s1 = t1 * t1 + t2 * t2 + t3 * t3;
                float s2 = t4 * t4 + t5 * t5 + t6 * t6;
                float s3 = t7 * t7;
#pragma unroll
                for (int o = 16; o; o >>= 1) {
                    s0 += __shfl_xor_sync(0xffffffffu, s0, o);
                    s1 += __shfl_xor_sync(0xffffffffu, s1, o);
                    s2 += __shfl_xor_sync(0xffffffffu, s2, o);
                    s3 += __shfl_xor_sync(0xffffffffu, s3, o);
                }
                float r0 = rsqrtf(s0 * (1.f / 32.f) + 1e-6f);
                float r1 = rsqrtf(s1 * (1.f / 96.f) + 1e-6f);
                float r2 = rsqrtf(s2 * (1.f / 96.f) + 1e-6f);
                float r3 = rsqrtf(s3 * (1.f / 32.f) + 1e-6f);
                t0 *= r0; t1 *= r1; t2 *= r1; t3 *= r1;
                t4 *= r2; t5 *= r2; t6 *= r2; t7 *= r3;
                float* tp = &sTp[(el * 32 + m) * 8];
                tp[0] = t0; tp[1] = t1; tp[2] = t2; tp[3] = t3;
                tp[4] = t4; tp[5] = t5; tp[6] = t6; tp[7] = t7;
                sF[el * 80 + m]      = t0;
                sF[el * 80 + 32 + m] = t7;
            }
        }
        __syncthreads();

        // F[64][80] @ Wc[80][256], f32x2 packed
        float4 bias4 = ((float4*)sB)[tCol];
        unsigned long long accA[8], accB[8];
#pragma unroll
        for (int i = 0; i < 8; i++) {
            accA[i] = pk2(bias4.x, bias4.y);
            accB[i] = pk2(bias4.z, bias4.w);
        }
        for (int kb = 0; kb < 80; kb += 4) {
            float4 fv[8];
#pragma unroll
            for (int i = 0; i < 8; i++)
                fv[i] = *(const float4*)&sF[(tRow * 8 + i) * 80 + kb];
#pragma unroll
            for (int kk = 0; kk < 4; kk++) {
                float4 w4 = ((const float4*)(sWc + (kb + kk) * 256))[tCol];
                unsigned long long wA = pk2(w4.x, w4.y);
                unsigned long long wB = pk2(w4.z, w4.w);
#pragma unroll
                for (int i = 0; i < 8; i++) {
                    float f = (kk == 0) ? fv[i].x : (kk == 1) ? fv[i].y
                            : (kk == 2) ? fv[i].z : fv[i].w;
                    unsigned long long ff = pk2(f, f);
                    fma2(accA[i], wA, ff);
                    fma2(accB[i], wB, ff);
                }
            }
        }

#pragma unroll
        for (int i = 0; i < 8; i++) {
            int el = tRow * 8 + i;
            long e = e0 + el;
            long r = active[e];
            float2 axy = upk2(accA[i]);
            float2 azw = upk2(accB[i]);
            float4 a = make_float4(axy.x, axy.y, azw.x, azw.y);
            if (tCol < 32) {
                int m2 = tCol;
                float* tp = &sTp[(el * 32 + m2) * 8];
                float4 ne;
                ne.x = a.x * tp[0] + a.y * tp[7];
                ne.y = a.z * tp[1] + a.w * tp[4];
                ne.z = a.z * tp[2] + a.w * tp[5];
                ne.w = a.z * tp[3] + a.w * tp[6];
                float4 b = *(const float4*)(equiv + r * 128 + m2 * 4);
                float4 o;
                o.x = c_old * b.x + c_new * ne.x;
                o.y = c_old * b.y + c_new * ne.y;
                o.z = c_old * b.z + c_new * ne.z;
                o.w = c_old * b.w + c_new * ne.w;
                *(float4*)(out + (long)E_CNT * 128 + r * 128 + m2 * 4) = o;
            } else {
                int jc = tCol - 32;
                float4 b = *(const float4*)(scal + r * 128 + jc * 4);
                float4 o;
                o.x = c_old * b.x + c_new * a.x;
                o.y = c_old * b.y + c_new * a.y;
                o.z = c_old * b.z + c_new * a.z;
                o.w = c_old * b.w + c_new * a.w;
                *(float4*)(out + r * 128 + jc * 4) = o;
            }
        }
    }
}

// ---------------- launch ----------------
extern "C" void kernel_launch(void* const* d_in, const int* in_sizes, int n_in,
                              void* d_out, int out_size)
{
    const float* scal  = (const float*)d_in[0];
    const float* equiv = (const float*)d_in[1];
    const float* ninv  = (const float*)d_in[2];
    const float* cond  = (const float*)d_in[3];
    const float* ucoef = (const float*)d_in[4];
    const float* W_env = (const float*)d_in[5];
    const float* b_env = (const float*)d_in[6];
    const float* Wq    = (const float*)d_in[7];
    const float* Wk    = (const float*)d_in[8];
    const float* W_mix = (const float*)d_in[9];
    const float* b_mix = (const float*)d_in[10];
    const float* W_sc  = (const float*)d_in[11];
    const float* b_sc  = (const float*)d_in[12];
    const int*   ec    = (const int*)d_in[13];
    const int*   act   = (const int*)d_in[14];
    float* out = (float*)d_out;

    // launch order: profiled launch (#3) = k_nodeA
    const int SMEMQP = (16384 + 8192) * 4;
    cudaFuncSetAttribute(k_QP, cudaFuncAttributeMaxDynamicSharedMemorySize, SMEMQP);
    k_QP<<<N_CNT / 32, 256, SMEMQP>>>(ninv, Wq, Wk, ec);   // 0 (hist fused)

    k_scan<<<1, 1024>>>();                                 // 1
    k_scatter<<<E_CNT / 256, 256>>>(ec);                   // 2

    const int SMEMA = (4096 + 8192 + 4352 + 256 + 16) * 4;
    cudaFuncSetAttribute(k_nodeA, cudaFuncAttributeMaxDynamicSharedMemorySize, SMEMA);
    k_nodeA<<<444, 128, SMEMA>>>(scal, equiv, W_env, b_env);   // 3 <- profiled

    const int SMEMB = (20480 + 256 + 5120 + 16384) * 4;
    cudaFuncSetAttribute(k_edgeB, cudaFuncAttributeMaxDynamicSharedMemorySize, SMEMB);
    k_edgeB<<<148, 512, SMEMB>>>(scal, equiv, cond, ucoef,
                                 W_mix, b_mix, W_sc, b_sc, ec, act, out);  // 4
}